// round 6
// baseline (speedup 1.0000x reference)
#include <cuda_runtime.h>
#include <cuda_fp16.h>
#include <cstdint>
#include <math.h>

// Problem dims
#define NB   32      // batch
#define NI   12      // input channels
#define NVV  128     // vertices
#define NHD  32      // conv hidden
#define NTT  100     // time steps
#define NHH  4096    // NH = V*H
#define NH3  12288   // 3*NH
#define NR   3200    // T*B rows
#define NBLK 128     // persistent recurrence blocks (<=148 SMs: co-resident)

// d_out region offsets (floats)
static const long OUT_STATES = 13107200L;   // B*NH*T
static const long OUT_HENC   = 26214400L;   // + B*NH*T
static const long OUT_CLS    = 26345472L;   // + B*NH

// ------------------------- scratch (device globals, no allocs) -----------
__device__ float    gSupport[NVV * NVV];
__device__ __half   gReprH[(long)NR * NHH];      // 26 MB
__device__ __half   gWih[(long)NH3 * NHH];       // 100 MB
__device__ __half   gWhh[(long)NH3 * NHH];       // 100 MB
__device__ float    gGx[(long)NR * NH3];         // 157 MB
__device__ __half   gHh[2][NB * NHH];            // double-buffered fp16 h
__device__ unsigned gBarCnt;                      // grid barrier arrive count
__device__ unsigned gBarPhase;                    // grid barrier phase (monotonic)

// ------------------------- cp.async helpers ------------------------------
__device__ __forceinline__ void cp_async16(void* smem, const void* gmem) {
    uint32_t s = (uint32_t)__cvta_generic_to_shared(smem);
    asm volatile("cp.async.cg.shared.global [%0], [%1], 16;\n" :: "r"(s), "l"(gmem));
}
__device__ __forceinline__ void cp_commit() {
    asm volatile("cp.async.commit_group;\n");
}
template <int N>
__device__ __forceinline__ void cp_wait() {
    asm volatile("cp.async.wait_group %0;\n" :: "n"(N));
}

// ------------------------- fp16 NT mma ----------------------------------
__device__ __forceinline__ void mma_m16n8k16(float* d, const uint32_t* a,
                                             uint32_t b0, uint32_t b1) {
    asm volatile(
        "mma.sync.aligned.m16n8k16.row.col.f32.f16.f16.f32 "
        "{%0,%1,%2,%3}, {%4,%5,%6,%7}, {%8,%9}, {%0,%1,%2,%3};\n"
        : "+f"(d[0]), "+f"(d[1]), "+f"(d[2]), "+f"(d[3])
        : "r"(a[0]), "r"(a[1]), "r"(a[2]), "r"(a[3]), "r"(b0), "r"(b1));
}

// ------------------------- weight conversion (vectorized) -----------------
__global__ void convert_weights_kernel(const float4* __restrict__ wih4,
                                       const float4* __restrict__ whh4) {
    long n4 = (long)NH3 * NHH / 4;
    long stride = (long)gridDim.x * blockDim.x;
    __half2* wih_o = (__half2*)gWih;
    __half2* whh_o = (__half2*)gWhh;
    for (long i = (long)blockIdx.x * blockDim.x + threadIdx.x; i < n4; i += stride) {
        float4 a = wih4[i];
        wih_o[2 * i]     = __floats2half2_rn(a.x, a.y);
        wih_o[2 * i + 1] = __floats2half2_rn(a.z, a.w);
        float4 b = whh4[i];
        whh_o[2 * i]     = __floats2half2_rn(b.x, b.y);
        whh_o[2 * i + 1] = __floats2half2_rn(b.z, b.w);
    }
}

// ------------------------- support = adj / (rowsum + 1e-6) ---------------
__global__ void support_kernel(const float* __restrict__ adj) {
    int w = threadIdx.x;  // 128 threads
    float s = 0.f;
    for (int v = 0; v < NVV; v++) s += adj[w * NVV + v];
    float inv = 1.f / (s + 1e-6f);
    for (int v = 0; v < NVV; v++) gSupport[w * NVV + v] = adj[w * NVV + v] * inv;
}

// ------------------------- repr: conv + 2x graph conv --------------------
__global__ void repr_kernel(const float* __restrict__ x,
                            const float* __restrict__ conv_w,
                            const float* __restrict__ conv_b,
                            float* __restrict__ d_out) {
    extern __shared__ float sm[];
    float* supT = sm;                  // [128][129]
    float* bufA = supT + 128 * 129;    // [32][132]
    float* bufB = bufA + 32 * 132;     // [32][132]
    float* xs   = bufB + 32 * 132;     // [12][128]

    int r = blockIdx.x;
    int t = r >> 5;
    int b = r & 31;
    int tid = threadIdx.x;

    for (int idx = tid; idx < NI * NVV; idx += 256) {
        int i = idx >> 7, v = idx & 127;
        xs[idx] = x[(((long)b * NI + i) * NVV + v) * NTT + t];
    }
    for (int idx = tid; idx < NVV * NVV; idx += 256) {
        int w = idx >> 7, v = idx & 127;
        supT[v * 129 + w] = gSupport[idx];
    }
    __syncthreads();

    for (int idx = tid; idx < NHD * NVV; idx += 256) {
        int h = idx >> 7, v = idx & 127;
        float a = conv_b[h];
#pragma unroll
        for (int i = 0; i < NI; i++) a += conv_w[h * NI + i] * xs[i * NVV + v];
        bufA[h * 132 + v] = a;
    }
    __syncthreads();

    int w0 = tid & 31;
    int h0 = tid >> 5;

    float acc1[4][4];
#pragma unroll
    for (int i = 0; i < 4; i++)
#pragma unroll
        for (int j = 0; j < 4; j++) acc1[i][j] = 0.f;
    for (int v = 0; v < NVV; v++) {
        float a[4], s[4];
#pragma unroll
        for (int i = 0; i < 4; i++) a[i] = bufA[(h0 + 8 * i) * 132 + v];
#pragma unroll
        for (int j = 0; j < 4; j++) s[j] = supT[v * 129 + w0 + 32 * j];
#pragma unroll
        for (int i = 0; i < 4; i++)
#pragma unroll
            for (int j = 0; j < 4; j++) acc1[i][j] += a[i] * s[j];
    }
    __syncthreads();
#pragma unroll
    for (int i = 0; i < 4; i++)
#pragma unroll
        for (int j = 0; j < 4; j++) bufB[(h0 + 8 * i) * 132 + w0 + 32 * j] = acc1[i][j];
    __syncthreads();

    float acc2[4][4];
#pragma unroll
    for (int i = 0; i < 4; i++)
#pragma unroll
        for (int j = 0; j < 4; j++) acc2[i][j] = 0.f;
    for (int v = 0; v < NVV; v++) {
        float a[4], s[4];
#pragma unroll
        for (int i = 0; i < 4; i++) a[i] = bufB[(h0 + 8 * i) * 132 + v];
#pragma unroll
        for (int j = 0; j < 4; j++) s[j] = supT[v * 129 + w0 + 32 * j];
#pragma unroll
        for (int i = 0; i < 4; i++)
#pragma unroll
            for (int j = 0; j < 4; j++) acc2[i][j] += a[i] * s[j];
    }

#pragma unroll
    for (int i = 0; i < 4; i++) {
#pragma unroll
        for (int j = 0; j < 4; j++) {
            int h = h0 + 8 * i, w = w0 + 32 * j;
            int n = h * NVV + w;
            float val = acc2[i][j];
            d_out[(long)b * (NHH * NTT) + (long)n * NTT + t] = val;
            gReprH[(long)r * NHH + n] = __float2half(val);
        }
    }
}

// ------------------------- pipelined gx GEMM (ST=4) -----------------------
// C[3200 x 12288](f32) = A[3200 x 4096](f16) @ W[12288 x 4096]^T(f16) + bias
__global__ void __launch_bounds__(256) gemm_gx_kernel(const float* __restrict__ bias) {
    constexpr int BM = 128, BN = 128, BK = 64, ST = 4, LD = 72;
    extern __shared__ __half smh[];
    __half* As = smh;
    __half* Ws = smh + ST * BM * LD;

    int tid = threadIdx.x;
    int warp = tid >> 5, lane = tid & 31;
    int g = lane >> 2, ti = lane & 3;
    int wm = warp & 1, wn = warp >> 1;

    long rowA0 = (long)blockIdx.y * BM;
    long rowW0 = (long)blockIdx.x * BN;

    const __half* A = gReprH;
    const __half* W = gWih;

    int ldrow = tid >> 3, ldseg = tid & 7;

#pragma unroll
    for (int s = 0; s < ST - 1; s++) {
        int k0 = s * BK;
#pragma unroll
        for (int i = 0; i < 4; i++) {
            int row = ldrow + i * 32;
            cp_async16(As + (s * BM + row) * LD + ldseg * 8,
                       A + (rowA0 + row) * (long)NHH + k0 + ldseg * 8);
        }
#pragma unroll
        for (int i = 0; i < 4; i++) {
            int row = ldrow + i * 32;
            cp_async16(Ws + (s * BN + row) * LD + ldseg * 8,
                       W + (rowW0 + row) * (long)NHH + k0 + ldseg * 8);
        }
        cp_commit();
    }

    float acc[4][4][4];
#pragma unroll
    for (int mt = 0; mt < 4; mt++)
#pragma unroll
        for (int nt = 0; nt < 4; nt++)
#pragma unroll
            for (int q = 0; q < 4; q++) acc[mt][nt][q] = 0.f;

    const int KT = NHH / BK;
    for (int kt = 0; kt < KT; kt++) {
        cp_wait<ST - 2>();
        __syncthreads();
        if (kt + ST - 1 < KT) {
            int s = (kt + ST - 1) % ST;
            int k0 = (kt + ST - 1) * BK;
#pragma unroll
            for (int i = 0; i < 4; i++) {
                int row = ldrow + i * 32;
                cp_async16(As + (s * BM + row) * LD + ldseg * 8,
                           A + (rowA0 + row) * (long)NHH + k0 + ldseg * 8);
            }
#pragma unroll
            for (int i = 0; i < 4; i++) {
                int row = ldrow + i * 32;
                cp_async16(Ws + (s * BN + row) * LD + ldseg * 8,
                           W + (rowW0 + row) * (long)NHH + k0 + ldseg * 8);
            }
        }
        cp_commit();  // every iter (tail alignment)

        const __half* Ab = As + (kt % ST) * BM * LD;
        const __half* Wb = Ws + (kt % ST) * BN * LD;

#pragma unroll
        for (int kk = 0; kk < BK; kk += 16) {
            uint32_t af[4][4];
#pragma unroll
            for (int mt = 0; mt < 4; mt++) {
                int rbase = wm * 64 + mt * 16;
                af[mt][0] = *(const uint32_t*)(Ab + (rbase + g)     * LD + kk + 2 * ti);
                af[mt][1] = *(const uint32_t*)(Ab + (rbase + g + 8) * LD + kk + 2 * ti);
                af[mt][2] = *(const uint32_t*)(Ab + (rbase + g)     * LD + kk + 8 + 2 * ti);
                af[mt][3] = *(const uint32_t*)(Ab + (rbase + g + 8) * LD + kk + 8 + 2 * ti);
            }
#pragma unroll
            for (int nt = 0; nt < 4; nt++) {
                int nb = wn * 32 + nt * 8 + g;
                uint32_t b0 = *(const uint32_t*)(Wb + nb * LD + kk + 2 * ti);
                uint32_t b1 = *(const uint32_t*)(Wb + nb * LD + kk + 8 + 2 * ti);
#pragma unroll
                for (int mt = 0; mt < 4; mt++) mma_m16n8k16(acc[mt][nt], af[mt], b0, b1);
            }
        }
    }

    float* C = gGx;
#pragma unroll
    for (int mt = 0; mt < 4; mt++) {
        long row = rowA0 + wm * 64 + mt * 16 + g;
#pragma unroll
        for (int nt = 0; nt < 4; nt++) {
            long col = rowW0 + wn * 32 + nt * 8 + 2 * ti;
            float bv0 = bias[col], bv1 = bias[col + 1];
            C[row * NH3 + col]           = acc[mt][nt][0] + bv0;
            C[row * NH3 + col + 1]       = acc[mt][nt][1] + bv1;
            C[(row + 8) * NH3 + col]     = acc[mt][nt][2] + bv0;
            C[(row + 8) * NH3 + col + 1] = acc[mt][nt][3] + bv1;
        }
    }
}

// ------------------------- h init (fp16 buffer only) ---------------------
__global__ void h_init_kernel(const float* __restrict__ h0) {
    int idx = blockIdx.x * blockDim.x + threadIdx.x;  // 32*4096
    gHh[0][idx] = __float2half(h0[idx & (NHH - 1)]);
}

// ------------------------- persistent GRU (continuous pipeline) ----------
// ONE launch, 100 steps, 128 co-resident blocks. Block j owns hidden cols
// [32j,32j+32) for all 3 gates; h kept in registers.
// Cross-step schedule: K-loop (wait<2>, mixed W+A groups) -> gate math ->
// issue next-step W stages (barrier-independent) -> grid barrier (hidden
// behind W loads) -> issue next-step A stages. Pipeline never drains.
// Steady state: 70 commit groups per step (64 loop + 3 W + 3 A).
__global__ void __launch_bounds__(256) gru_persistent_kernel(
    const float* __restrict__ h0,
    const float* __restrict__ b_hh,
    float* __restrict__ d_out) {
    constexpr int BK = 64, ST = 4, LD = 72, WR = 96, AR = 32;
    extern __shared__ char smraw[];
    __half* As   = (__half*)smraw;                // ST * 32 * LD
    __half* Ws   = As + ST * AR * LD;             // ST * 96 * LD
    float*  gh_s = (float*)(Ws + ST * WR * LD);   // 32 * 100

    int tid = threadIdx.x;
    int warp = tid >> 5, lane = tid & 31;
    int g = lane >> 2, ti = lane & 3;
    int wm = warp & 1, wn = warp >> 1;            // 2 x 4, warp tile 16 x 24
    int n0 = blockIdx.x * 32;

    int ldrow = tid >> 3, ldseg = tid & 7;

    // fixed W row pointers (3 per thread; same every step)
    const __half* wptr[3];
#pragma unroll
    for (int i = 0; i < 3; i++) {
        int lr = ldrow + i * 32;
        long wr = (long)(lr >> 5) * NHH + n0 + (lr & 31);
        wptr[i] = gWhh + wr * (long)NHH + ldseg * 8;
    }

    // per-thread gate lane constants: idx = tid + i*256 -> (b, n)
    int pb[4], pn[4];
    float hreg[4], bhr[4], bhz[4], bhn[4];
#pragma unroll
    for (int i = 0; i < 4; i++) {
        int idx = tid + i * 256;
        pb[i] = idx >> 5;
        pn[i] = n0 + (idx & 31);
        hreg[i] = h0[pn[i]];
        bhr[i] = b_hh[pn[i]];
        bhz[i] = b_hh[NHH + pn[i]];
        bhn[i] = b_hh[2 * NHH + pn[i]];
    }

    // barrier base phase (read BEFORE first arrival -> replay-safe)
    unsigned barBase = *(volatile unsigned*)&gBarPhase;

    // prologue for t=0: 3 W-only groups, then 3 A-only groups (h0 ready)
#pragma unroll
    for (int s = 0; s < ST - 1; s++) {
        int k0 = s * BK;
#pragma unroll
        for (int i = 0; i < 3; i++) {
            int lr = ldrow + i * 32;
            cp_async16(Ws + (s * WR + lr) * LD + ldseg * 8, wptr[i] + k0);
        }
        cp_commit();
    }
    {
        const __half* ap0 = gHh[0] + ldrow * NHH + ldseg * 8;
#pragma unroll
        for (int s = 0; s < ST - 1; s++) {
            cp_async16(As + (s * AR + ldrow) * LD + ldseg * 8, ap0 + s * BK);
            cp_commit();
        }
    }

    const int KT = NHH / BK;  // 64
    for (int t = 0; t < NTT; t++) {
        const __half* aptr = gHh[t & 1] + ldrow * NHH + ldseg * 8;
        __half* Aout = gHh[(t + 1) & 1];

        // prefetch gx for this step (independent of pipeline & barrier)
        float pxr[4], pxz[4], pxn[4];
#pragma unroll
        for (int i = 0; i < 4; i++) {
            long gxr = ((long)(t * NB + pb[i])) * NH3 + pn[i];
            pxr[i] = gGx[gxr];
            pxz[i] = gGx[gxr + NHH];
            pxn[i] = gGx[gxr + 2 * NHH];
        }

        float acc[3][4];
#pragma unroll
        for (int nt = 0; nt < 3; nt++)
#pragma unroll
            for (int q = 0; q < 4; q++) acc[nt][q] = 0.f;

        for (int kt = 0; kt < KT; kt++) {
            cp_wait<2>();
            __syncthreads();
            if (kt + 3 < KT) {
                int s = (kt + 3) & 3;
                int k0 = (kt + 3) * BK;
                cp_async16(As + (s * AR + ldrow) * LD + ldseg * 8, aptr + k0);
#pragma unroll
                for (int i = 0; i < 3; i++) {
                    int lr = ldrow + i * 32;
                    cp_async16(Ws + (s * WR + lr) * LD + ldseg * 8, wptr[i] + k0);
                }
            }
            cp_commit();  // every iteration (tail alignment)

            const __half* Ab = As + (kt & 3) * AR * LD;
            const __half* Wb = Ws + (kt & 3) * WR * LD;

#pragma unroll
            for (int kk = 0; kk < BK; kk += 16) {
                uint32_t af[4];
                int rbase = wm * 16;
                af[0] = *(const uint32_t*)(Ab + (rbase + g)     * LD + kk + 2 * ti);
                af[1] = *(const uint32_t*)(Ab + (rbase + g + 8) * LD + kk + 2 * ti);
                af[2] = *(const uint32_t*)(Ab + (rbase + g)     * LD + kk + 8 + 2 * ti);
                af[3] = *(const uint32_t*)(Ab + (rbase + g + 8) * LD + kk + 8 + 2 * ti);
#pragma unroll
                for (int nt = 0; nt < 3; nt++) {
                    int nb = (wn * 3 + nt) * 8 + g;
                    uint32_t b0 = *(const uint32_t*)(Wb + nb * LD + kk + 2 * ti);
                    uint32_t b1 = *(const uint32_t*)(Wb + nb * LD + kk + 8 + 2 * ti);
                    mma_m16n8k16(acc[nt], af, b0, b1);
                }
            }
        }

        // gh -> smem [batch m][col c]
#pragma unroll
        for (int nt = 0; nt < 3; nt++) {
            int c = (wn * 3 + nt) * 8 + 2 * ti;
            int m = wm * 16 + g;
            gh_s[m * 100 + c]           = acc[nt][0];
            gh_s[m * 100 + c + 1]       = acc[nt][1];
            gh_s[(m + 8) * 100 + c]     = acc[nt][2];
            gh_s[(m + 8) * 100 + c + 1] = acc[nt][3];
        }
        __syncthreads();  // all warps past K-loop; gh_s visible

        // gate math (h in registers, gx prefetched)
#pragma unroll
        for (int i = 0; i < 4; i++) {
            int b = pb[i], nl = pn[i] - n0, n = pn[i];

            float hr = gh_s[b * 100 + nl]      + bhr[i];
            float hz = gh_s[b * 100 + 32 + nl] + bhz[i];
            float hn = gh_s[b * 100 + 64 + nl] + bhn[i];

            float r = 1.f / (1.f + expf(-(pxr[i] + hr)));
            float z = 1.f / (1.f + expf(-(pxz[i] + hz)));
            float nn = tanhf(pxn[i] + r * hn);
            float hnew = (1.f - z) * nn + z * hreg[i];
            hreg[i] = hnew;

            Aout[b * NHH + n] = __float2half(hnew);
            d_out[OUT_STATES + (long)b * (NHH * NTT) + (long)n * NTT + t] = hnew;
            if (t == NTT - 1) d_out[OUT_HENC + b * NHH + n] = hnew;
        }

        if (t < NTT - 1) {
            // issue next-step W stages BEFORE the barrier (barrier-independent;
            // stages 0..2 were last computed at kt=60..62, all warps done)
#pragma unroll
            for (int s = 0; s < ST - 1; s++) {
                int k0 = s * BK;
#pragma unroll
                for (int i = 0; i < 3; i++) {
                    int lr = ldrow + i * 32;
                    cp_async16(Ws + (s * WR + lr) * LD + ldseg * 8, wptr[i] + k0);
                }
                cp_commit();
            }

            // ---- grid barrier (hidden behind the W loads above) ----
            __syncthreads();
            if (tid == 0) {
                __threadfence();
                unsigned arrived = atomicAdd(&gBarCnt, 1u);
                unsigned target = barBase + (unsigned)(t + 1);
                if (arrived == NBLK - 1) {
                    gBarCnt = 0;
                    __threadfence();
                    atomicExch(&gBarPhase, target);
                } else {
                    while ((int)(atomicAdd(&gBarPhase, 0u) - target) < 0) {
                        __nanosleep(32);
                    }
                }
            }
            __syncthreads();

            // issue next-step A stages (h for t+1 now globally ready)
            const __half* ap2 = gHh[(t + 1) & 1] + ldrow * NHH + ldseg * 8;
#pragma unroll
            for (int s = 0; s < ST - 1; s++) {
                cp_async16(As + (s * AR + ldrow) * LD + ldseg * 8, ap2 + s * BK);
                cp_commit();
            }
        }
    }
    cp_wait<0>();  // drain before exit
}

// ------------------------- classifier ------------------------------------
__global__ void classifier_kernel(const float* __restrict__ w1, const float* __restrict__ b1,
                                  const float* __restrict__ w2, const float* __restrict__ b2,
                                  float* __restrict__ d_out) {
    __shared__ float hid[300];
    int b = blockIdx.x;
    int tid = threadIdx.x, warp = tid >> 5, lane = tid & 31;
    const float* hb = d_out + OUT_HENC + (long)b * NHH;

    for (int j = warp; j < 300; j += 8) {
        float s = 0.f;
        for (int k = lane; k < NHH; k += 32) s += hb[k] * w1[(long)j * NHH + k];
#pragma unroll
        for (int off = 16; off; off >>= 1) s += __shfl_xor_sync(0xffffffffu, s, off);
        if (lane == 0) hid[j] = fmaxf(s + b1[j], 0.f);
    }
    __syncthreads();
    if (warp < 2) {
        float s = 0.f;
        for (int j = lane; j < 300; j += 32) s += hid[j] * w2[warp * 300 + j];
#pragma unroll
        for (int off = 16; off; off >>= 1) s += __shfl_xor_sync(0xffffffffu, s, off);
        if (lane == 0) d_out[OUT_CLS + b * 2 + warp] = s + b2[warp];
    }
}

// ------------------------- launch ----------------------------------------
extern "C" void kernel_launch(void* const* d_in, const int* in_sizes, int n_in,
                              void* d_out, int out_size) {
    const float* x      = (const float*)d_in[0];
    const float* adj    = (const float*)d_in[1];
    const float* h0     = (const float*)d_in[3];
    const float* conv_w = (const float*)d_in[4];
    const float* conv_b = (const float*)d_in[5];
    const float* w_ih   = (const float*)d_in[6];
    const float* w_hh   = (const float*)d_in[7];
    const float* b_ih   = (const float*)d_in[8];
    const float* b_hh   = (const float*)d_in[9];
    const float* cls_w1 = (const float*)d_in[10];
    const float* cls_b1 = (const float*)d_in[11];
    const float* cls_w2 = (const float*)d_in[12];
    const float* cls_b2 = (const float*)d_in[13];
    float* out = (float*)d_out;

    const int REPR_SMEM = (128 * 129 + 32 * 132 + 32 * 132 + 12 * 128) * 4;  // 105984
    const int GX_SMEM   = 4 * (128 + 128) * 72 * 2;                          // 147456
    const int PS_SMEM   = 4 * (32 + 96) * 72 * 2 + 32 * 100 * 4;             // 86528
    cudaFuncSetAttribute(repr_kernel, cudaFuncAttributeMaxDynamicSharedMemorySize, REPR_SMEM);
    cudaFuncSetAttribute(gemm_gx_kernel, cudaFuncAttributeMaxDynamicSharedMemorySize, GX_SMEM);
    cudaFuncSetAttribute(gru_persistent_kernel, cudaFuncAttributeMaxDynamicSharedMemorySize, PS_SMEM);

    convert_weights_kernel<<<2048, 256>>>((const float4*)w_ih, (const float4*)w_hh);
    support_kernel<<<1, 128>>>(adj);
    repr_kernel<<<NR, 256, REPR_SMEM>>>(x, conv_w, conv_b, out);
    h_init_kernel<<<512, 256>>>(h0);

    gemm_gx_kernel<<<dim3(96, 25), 256, GX_SMEM>>>(b_ih);

    gru_persistent_kernel<<<NBLK, 256, PS_SMEM>>>(h0, b_hh, out);

    classifier_kernel<<<NB, 256>>>(cls_w1, cls_b1, cls_w2, cls_b2, out);
}

// round 7
// speedup vs baseline: 1.0570x; 1.0570x over previous
#include <cuda_runtime.h>
#include <cuda_fp16.h>
#include <cstdint>
#include <math.h>

// Problem dims
#define NB   32      // batch
#define NI   12      // input channels
#define NVV  128     // vertices
#define NHD  32      // conv hidden
#define NTT  100     // time steps
#define NHH  4096    // NH = V*H
#define NH3  12288   // 3*NH
#define NR   3200    // T*B rows
#define NBLK 128     // persistent recurrence blocks (<=148 SMs: co-resident)

// d_out region offsets (floats)
static const long OUT_STATES = 13107200L;   // B*NH*T
static const long OUT_HENC   = 26214400L;   // + B*NH*T
static const long OUT_CLS    = 26345472L;   // + B*NH

// ------------------------- scratch (device globals, no allocs) -----------
__device__ float    gSupport[NVV * NVV];
__device__ __half   gReprH[(long)NR * NHH];      // 26 MB
__device__ __half   gWih[(long)NH3 * NHH];       // 100 MB
__device__ __half   gWhh[(long)NH3 * NHH];       // 100 MB
__device__ float    gGx[(long)NR * NH3];         // 157 MB
__device__ __half   gHh[2][NB * NHH];            // double-buffered fp16 h
__device__ unsigned gBarCnt;                      // grid barrier arrive count
__device__ unsigned gBarPhase;                    // grid barrier phase (monotonic)

// ------------------------- cp.async helpers ------------------------------
__device__ __forceinline__ void cp_async16(void* smem, const void* gmem) {
    uint32_t s = (uint32_t)__cvta_generic_to_shared(smem);
    asm volatile("cp.async.cg.shared.global [%0], [%1], 16;\n" :: "r"(s), "l"(gmem));
}
__device__ __forceinline__ void cp_commit() {
    asm volatile("cp.async.commit_group;\n");
}
template <int N>
__device__ __forceinline__ void cp_wait() {
    asm volatile("cp.async.wait_group %0;\n" :: "n"(N));
}

// ------------------------- fp16 NT mma ----------------------------------
__device__ __forceinline__ void mma_m16n8k16(float* d, const uint32_t* a,
                                             uint32_t b0, uint32_t b1) {
    asm volatile(
        "mma.sync.aligned.m16n8k16.row.col.f32.f16.f16.f32 "
        "{%0,%1,%2,%3}, {%4,%5,%6,%7}, {%8,%9}, {%0,%1,%2,%3};\n"
        : "+f"(d[0]), "+f"(d[1]), "+f"(d[2]), "+f"(d[3])
        : "r"(a[0]), "r"(a[1]), "r"(a[2]), "r"(a[3]), "r"(b0), "r"(b1));
}

// ------------------------- weight conversion (vectorized) -----------------
__global__ void convert_weights_kernel(const float4* __restrict__ wih4,
                                       const float4* __restrict__ whh4) {
    long n4 = (long)NH3 * NHH / 4;
    long stride = (long)gridDim.x * blockDim.x;
    __half2* wih_o = (__half2*)gWih;
    __half2* whh_o = (__half2*)gWhh;
    for (long i = (long)blockIdx.x * blockDim.x + threadIdx.x; i < n4; i += stride) {
        float4 a = wih4[i];
        wih_o[2 * i]     = __floats2half2_rn(a.x, a.y);
        wih_o[2 * i + 1] = __floats2half2_rn(a.z, a.w);
        float4 b = whh4[i];
        whh_o[2 * i]     = __floats2half2_rn(b.x, b.y);
        whh_o[2 * i + 1] = __floats2half2_rn(b.z, b.w);
    }
}

// ------------------------- support = adj / (rowsum + 1e-6) ---------------
__global__ void support_kernel(const float* __restrict__ adj) {
    int w = threadIdx.x;  // 128 threads
    float s = 0.f;
    for (int v = 0; v < NVV; v++) s += adj[w * NVV + v];
    float inv = 1.f / (s + 1e-6f);
    for (int v = 0; v < NVV; v++) gSupport[w * NVV + v] = adj[w * NVV + v] * inv;
}

// ------------------------- repr: conv + 2x graph conv --------------------
__global__ void repr_kernel(const float* __restrict__ x,
                            const float* __restrict__ conv_w,
                            const float* __restrict__ conv_b,
                            float* __restrict__ d_out) {
    extern __shared__ float sm[];
    float* supT = sm;                  // [128][129]
    float* bufA = supT + 128 * 129;    // [32][132]
    float* bufB = bufA + 32 * 132;     // [32][132]
    float* xs   = bufB + 32 * 132;     // [12][128]

    int r = blockIdx.x;
    int t = r >> 5;
    int b = r & 31;
    int tid = threadIdx.x;

    for (int idx = tid; idx < NI * NVV; idx += 256) {
        int i = idx >> 7, v = idx & 127;
        xs[idx] = x[(((long)b * NI + i) * NVV + v) * NTT + t];
    }
    for (int idx = tid; idx < NVV * NVV; idx += 256) {
        int w = idx >> 7, v = idx & 127;
        supT[v * 129 + w] = gSupport[idx];
    }
    __syncthreads();

    for (int idx = tid; idx < NHD * NVV; idx += 256) {
        int h = idx >> 7, v = idx & 127;
        float a = conv_b[h];
#pragma unroll
        for (int i = 0; i < NI; i++) a += conv_w[h * NI + i] * xs[i * NVV + v];
        bufA[h * 132 + v] = a;
    }
    __syncthreads();

    int w0 = tid & 31;
    int h0 = tid >> 5;

    float acc1[4][4];
#pragma unroll
    for (int i = 0; i < 4; i++)
#pragma unroll
        for (int j = 0; j < 4; j++) acc1[i][j] = 0.f;
    for (int v = 0; v < NVV; v++) {
        float a[4], s[4];
#pragma unroll
        for (int i = 0; i < 4; i++) a[i] = bufA[(h0 + 8 * i) * 132 + v];
#pragma unroll
        for (int j = 0; j < 4; j++) s[j] = supT[v * 129 + w0 + 32 * j];
#pragma unroll
        for (int i = 0; i < 4; i++)
#pragma unroll
            for (int j = 0; j < 4; j++) acc1[i][j] += a[i] * s[j];
    }
    __syncthreads();
#pragma unroll
    for (int i = 0; i < 4; i++)
#pragma unroll
        for (int j = 0; j < 4; j++) bufB[(h0 + 8 * i) * 132 + w0 + 32 * j] = acc1[i][j];
    __syncthreads();

    float acc2[4][4];
#pragma unroll
    for (int i = 0; i < 4; i++)
#pragma unroll
        for (int j = 0; j < 4; j++) acc2[i][j] = 0.f;
    for (int v = 0; v < NVV; v++) {
        float a[4], s[4];
#pragma unroll
        for (int i = 0; i < 4; i++) a[i] = bufB[(h0 + 8 * i) * 132 + v];
#pragma unroll
        for (int j = 0; j < 4; j++) s[j] = supT[v * 129 + w0 + 32 * j];
#pragma unroll
        for (int i = 0; i < 4; i++)
#pragma unroll
            for (int j = 0; j < 4; j++) acc2[i][j] += a[i] * s[j];
    }

#pragma unroll
    for (int i = 0; i < 4; i++) {
#pragma unroll
        for (int j = 0; j < 4; j++) {
            int h = h0 + 8 * i, w = w0 + 32 * j;
            int n = h * NVV + w;
            float val = acc2[i][j];
            d_out[(long)b * (NHH * NTT) + (long)n * NTT + t] = val;
            gReprH[(long)r * NHH + n] = __float2half(val);
        }
    }
}

// ------------------------- pipelined gx GEMM (ST=4) -----------------------
// C[3200 x 12288](f32) = A[3200 x 4096](f16) @ W[12288 x 4096]^T(f16) + bias
// Grid transposed (x = M-tile, y = N-tile): a concurrent wave shares few
// W tiles and the whole A (L2-resident) -> DRAM reads W once + A once.
__global__ void __launch_bounds__(256) gemm_gx_kernel(const float* __restrict__ bias) {
    constexpr int BM = 128, BN = 128, BK = 64, ST = 4, LD = 72;
    extern __shared__ __half smh[];
    __half* As = smh;
    __half* Ws = smh + ST * BM * LD;

    int tid = threadIdx.x;
    int warp = tid >> 5, lane = tid & 31;
    int g = lane >> 2, ti = lane & 3;
    int wm = warp & 1, wn = warp >> 1;

    long rowA0 = (long)blockIdx.x * BM;   // M-tile (25)
    long rowW0 = (long)blockIdx.y * BN;   // N-tile (96)

    const __half* A = gReprH;
    const __half* W = gWih;

    int ldrow = tid >> 3, ldseg = tid & 7;

#pragma unroll
    for (int s = 0; s < ST - 1; s++) {
        int k0 = s * BK;
#pragma unroll
        for (int i = 0; i < 4; i++) {
            int row = ldrow + i * 32;
            cp_async16(As + (s * BM + row) * LD + ldseg * 8,
                       A + (rowA0 + row) * (long)NHH + k0 + ldseg * 8);
        }
#pragma unroll
        for (int i = 0; i < 4; i++) {
            int row = ldrow + i * 32;
            cp_async16(Ws + (s * BN + row) * LD + ldseg * 8,
                       W + (rowW0 + row) * (long)NHH + k0 + ldseg * 8);
        }
        cp_commit();
    }

    float acc[4][4][4];
#pragma unroll
    for (int mt = 0; mt < 4; mt++)
#pragma unroll
        for (int nt = 0; nt < 4; nt++)
#pragma unroll
            for (int q = 0; q < 4; q++) acc[mt][nt][q] = 0.f;

    const int KT = NHH / BK;
    for (int kt = 0; kt < KT; kt++) {
        cp_wait<ST - 2>();
        __syncthreads();
        if (kt + ST - 1 < KT) {
            int s = (kt + ST - 1) % ST;
            int k0 = (kt + ST - 1) * BK;
#pragma unroll
            for (int i = 0; i < 4; i++) {
                int row = ldrow + i * 32;
                cp_async16(As + (s * BM + row) * LD + ldseg * 8,
                           A + (rowA0 + row) * (long)NHH + k0 + ldseg * 8);
            }
#pragma unroll
            for (int i = 0; i < 4; i++) {
                int row = ldrow + i * 32;
                cp_async16(Ws + (s * BN + row) * LD + ldseg * 8,
                           W + (rowW0 + row) * (long)NHH + k0 + ldseg * 8);
            }
        }
        cp_commit();  // every iter (tail alignment)

        const __half* Ab = As + (kt % ST) * BM * LD;
        const __half* Wb = Ws + (kt % ST) * BN * LD;

#pragma unroll
        for (int kk = 0; kk < BK; kk += 16) {
            uint32_t af[4][4];
#pragma unroll
            for (int mt = 0; mt < 4; mt++) {
                int rbase = wm * 64 + mt * 16;
                af[mt][0] = *(const uint32_t*)(Ab + (rbase + g)     * LD + kk + 2 * ti);
                af[mt][1] = *(const uint32_t*)(Ab + (rbase + g + 8) * LD + kk + 2 * ti);
                af[mt][2] = *(const uint32_t*)(Ab + (rbase + g)     * LD + kk + 8 + 2 * ti);
                af[mt][3] = *(const uint32_t*)(Ab + (rbase + g + 8) * LD + kk + 8 + 2 * ti);
            }
#pragma unroll
            for (int nt = 0; nt < 4; nt++) {
                int nb = wn * 32 + nt * 8 + g;
                uint32_t b0 = *(const uint32_t*)(Wb + nb * LD + kk + 2 * ti);
                uint32_t b1 = *(const uint32_t*)(Wb + nb * LD + kk + 8 + 2 * ti);
#pragma unroll
                for (int mt = 0; mt < 4; mt++) mma_m16n8k16(acc[mt][nt], af[mt], b0, b1);
            }
        }
    }

    float* C = gGx;
#pragma unroll
    for (int mt = 0; mt < 4; mt++) {
        long row = rowA0 + wm * 64 + mt * 16 + g;
#pragma unroll
        for (int nt = 0; nt < 4; nt++) {
            long col = rowW0 + wn * 32 + nt * 8 + 2 * ti;
            float bv0 = bias[col], bv1 = bias[col + 1];
            C[row * NH3 + col]           = acc[mt][nt][0] + bv0;
            C[row * NH3 + col + 1]       = acc[mt][nt][1] + bv1;
            C[(row + 8) * NH3 + col]     = acc[mt][nt][2] + bv0;
            C[(row + 8) * NH3 + col + 1] = acc[mt][nt][3] + bv1;
        }
    }
}

// ------------------------- h init (fp16 buffer only) ---------------------
__global__ void h_init_kernel(const float* __restrict__ h0) {
    int idx = blockIdx.x * blockDim.x + threadIdx.x;  // 32*4096
    gHh[0][idx] = __float2half(h0[idx & (NHH - 1)]);
}

// ------------------------- persistent GRU (deep pipeline, ST=8) ----------
// ONE launch, 100 steps, 128 co-resident blocks. Block j owns hidden cols
// [32j,32j+32) for all 3 gates; h kept in registers.
// ST=8: 6 commit-groups (~96KB) in flight per SM to cover DRAM-class
// latency when W_hh thrashes L2. Group alignment: one commit per loop
// iteration; prologue/inter-step = 7 W groups + 7 A groups; compute at kt
// needs the 8th-newest group -> wait<6> guarantees it.
__global__ void __launch_bounds__(256) gru_persistent_kernel(
    const float* __restrict__ h0,
    const float* __restrict__ b_hh,
    float* __restrict__ d_out) {
    constexpr int BK = 64, ST = 8, LD = 72, WR = 96, AR = 32;
    extern __shared__ char smraw[];
    __half* As   = (__half*)smraw;                // ST * 32 * LD
    __half* Ws   = As + ST * AR * LD;             // ST * 96 * LD
    float*  gh_s = (float*)(Ws + ST * WR * LD);   // 32 * 100

    int tid = threadIdx.x;
    int warp = tid >> 5, lane = tid & 31;
    int g = lane >> 2, ti = lane & 3;
    int wm = warp & 1, wn = warp >> 1;            // 2 x 4, warp tile 16 x 24
    int n0 = blockIdx.x * 32;

    int ldrow = tid >> 3, ldseg = tid & 7;

    // fixed W row pointers (3 per thread; same every step)
    const __half* wptr[3];
#pragma unroll
    for (int i = 0; i < 3; i++) {
        int lr = ldrow + i * 32;
        long wr = (long)(lr >> 5) * NHH + n0 + (lr & 31);
        wptr[i] = gWhh + wr * (long)NHH + ldseg * 8;
    }

    // per-thread gate lane constants: idx = tid + i*256 -> (b, n)
    int pb[4], pn[4];
    float hreg[4], bhr[4], bhz[4], bhn[4];
#pragma unroll
    for (int i = 0; i < 4; i++) {
        int idx = tid + i * 256;
        pb[i] = idx >> 5;
        pn[i] = n0 + (idx & 31);
        hreg[i] = h0[pn[i]];
        bhr[i] = b_hh[pn[i]];
        bhz[i] = b_hh[NHH + pn[i]];
        bhn[i] = b_hh[2 * NHH + pn[i]];
    }

    // barrier base phase (read BEFORE first arrival -> replay-safe)
    unsigned barBase = *(volatile unsigned*)&gBarPhase;

    // prologue for t=0: ST-1 W-only groups, then ST-1 A-only groups
#pragma unroll
    for (int s = 0; s < ST - 1; s++) {
        int k0 = s * BK;
#pragma unroll
        for (int i = 0; i < 3; i++) {
            int lr = ldrow + i * 32;
            cp_async16(Ws + (s * WR + lr) * LD + ldseg * 8, wptr[i] + k0);
        }
        cp_commit();
    }
    {
        const __half* ap0 = gHh[0] + ldrow * NHH + ldseg * 8;
#pragma unroll
        for (int s = 0; s < ST - 1; s++) {
            cp_async16(As + (s * AR + ldrow) * LD + ldseg * 8, ap0 + s * BK);
            cp_commit();
        }
    }

    const int KT = NHH / BK;  // 64
    for (int t = 0; t < NTT; t++) {
        const __half* aptr = gHh[t & 1] + ldrow * NHH + ldseg * 8;
        __half* Aout = gHh[(t + 1) & 1];

        // prefetch gx for this step (independent of pipeline & barrier)
        float pxr[4], pxz[4], pxn[4];
#pragma unroll
        for (int i = 0; i < 4; i++) {
            long gxr = ((long)(t * NB + pb[i])) * NH3 + pn[i];
            pxr[i] = gGx[gxr];
            pxz[i] = gGx[gxr + NHH];
            pxn[i] = gGx[gxr + 2 * NHH];
        }

        float acc[3][4];
#pragma unroll
        for (int nt = 0; nt < 3; nt++)
#pragma unroll
            for (int q = 0; q < 4; q++) acc[nt][q] = 0.f;

        for (int kt = 0; kt < KT; kt++) {
            cp_wait<ST - 2>();
            __syncthreads();
            if (kt + ST - 1 < KT) {
                int s = (kt + ST - 1) & (ST - 1);
                int k0 = (kt + ST - 1) * BK;
                cp_async16(As + (s * AR + ldrow) * LD + ldseg * 8, aptr + k0);
#pragma unroll
                for (int i = 0; i < 3; i++) {
                    int lr = ldrow + i * 32;
                    cp_async16(Ws + (s * WR + lr) * LD + ldseg * 8, wptr[i] + k0);
                }
            }
            cp_commit();  // every iteration (tail alignment)

            const __half* Ab = As + (kt & (ST - 1)) * AR * LD;
            const __half* Wb = Ws + (kt & (ST - 1)) * WR * LD;

#pragma unroll
            for (int kk = 0; kk < BK; kk += 16) {
                uint32_t af[4];
                int rbase = wm * 16;
                af[0] = *(const uint32_t*)(Ab + (rbase + g)     * LD + kk + 2 * ti);
                af[1] = *(const uint32_t*)(Ab + (rbase + g + 8) * LD + kk + 2 * ti);
                af[2] = *(const uint32_t*)(Ab + (rbase + g)     * LD + kk + 8 + 2 * ti);
                af[3] = *(const uint32_t*)(Ab + (rbase + g + 8) * LD + kk + 8 + 2 * ti);
#pragma unroll
                for (int nt = 0; nt < 3; nt++) {
                    int nb = (wn * 3 + nt) * 8 + g;
                    uint32_t b0 = *(const uint32_t*)(Wb + nb * LD + kk + 2 * ti);
                    uint32_t b1 = *(const uint32_t*)(Wb + nb * LD + kk + 8 + 2 * ti);
                    mma_m16n8k16(acc[nt], af, b0, b1);
                }
            }
        }

        // gh -> smem [batch m][col c]
#pragma unroll
        for (int nt = 0; nt < 3; nt++) {
            int c = (wn * 3 + nt) * 8 + 2 * ti;
            int m = wm * 16 + g;
            gh_s[m * 100 + c]           = acc[nt][0];
            gh_s[m * 100 + c + 1]       = acc[nt][1];
            gh_s[(m + 8) * 100 + c]     = acc[nt][2];
            gh_s[(m + 8) * 100 + c + 1] = acc[nt][3];
        }
        __syncthreads();  // all warps past K-loop; gh_s visible

        // gate math (h in registers, gx prefetched)
#pragma unroll
        for (int i = 0; i < 4; i++) {
            int b = pb[i], nl = pn[i] - n0, n = pn[i];

            float hr = gh_s[b * 100 + nl]      + bhr[i];
            float hz = gh_s[b * 100 + 32 + nl] + bhz[i];
            float hn = gh_s[b * 100 + 64 + nl] + bhn[i];

            float r = 1.f / (1.f + expf(-(pxr[i] + hr)));
            float z = 1.f / (1.f + expf(-(pxz[i] + hz)));
            float nn = tanhf(pxn[i] + r * hn);
            float hnew = (1.f - z) * nn + z * hreg[i];
            hreg[i] = hnew;

            Aout[b * NHH + n] = __float2half(hnew);
            d_out[OUT_STATES + (long)b * (NHH * NTT) + (long)n * NTT + t] = hnew;
            if (t == NTT - 1) d_out[OUT_HENC + b * NHH + n] = hnew;
        }

        if (t < NTT - 1) {
            // issue next-step W stages BEFORE the barrier (barrier-independent;
            // stages 0..ST-2 all consumed by end of this K-loop)
#pragma unroll
            for (int s = 0; s < ST - 1; s++) {
                int k0 = s * BK;
#pragma unroll
                for (int i = 0; i < 3; i++) {
                    int lr = ldrow + i * 32;
                    cp_async16(Ws + (s * WR + lr) * LD + ldseg * 8, wptr[i] + k0);
                }
                cp_commit();
            }

            // ---- grid barrier (hidden behind the W loads above) ----
            __syncthreads();
            if (tid == 0) {
                __threadfence();
                unsigned arrived = atomicAdd(&gBarCnt, 1u);
                unsigned target = barBase + (unsigned)(t + 1);
                if (arrived == NBLK - 1) {
                    gBarCnt = 0;
                    __threadfence();
                    atomicExch(&gBarPhase, target);
                } else {
                    while ((int)(atomicAdd(&gBarPhase, 0u) - target) < 0) {
                        __nanosleep(32);
                    }
                }
            }
            __syncthreads();

            // issue next-step A stages (h for t+1 now globally ready)
            const __half* ap2 = gHh[(t + 1) & 1] + ldrow * NHH + ldseg * 8;
#pragma unroll
            for (int s = 0; s < ST - 1; s++) {
                cp_async16(As + (s * AR + ldrow) * LD + ldseg * 8, ap2 + s * BK);
                cp_commit();
            }
        }
    }
    cp_wait<0>();  // drain before exit
}

// ------------------------- classifier ------------------------------------
__global__ void classifier_kernel(const float* __restrict__ w1, const float* __restrict__ b1,
                                  const float* __restrict__ w2, const float* __restrict__ b2,
                                  float* __restrict__ d_out) {
    __shared__ float hid[300];
    int b = blockIdx.x;
    int tid = threadIdx.x, warp = tid >> 5, lane = tid & 31;
    const float* hb = d_out + OUT_HENC + (long)b * NHH;

    for (int j = warp; j < 300; j += 8) {
        float s = 0.f;
        for (int k = lane; k < NHH; k += 32) s += hb[k] * w1[(long)j * NHH + k];
#pragma unroll
        for (int off = 16; off; off >>= 1) s += __shfl_xor_sync(0xffffffffu, s, off);
        if (lane == 0) hid[j] = fmaxf(s + b1[j], 0.f);
    }
    __syncthreads();
    if (warp < 2) {
        float s = 0.f;
        for (int j = lane; j < 300; j += 32) s += hid[j] * w2[warp * 300 + j];
#pragma unroll
        for (int off = 16; off; off >>= 1) s += __shfl_xor_sync(0xffffffffu, s, off);
        if (lane == 0) d_out[OUT_CLS + b * 2 + warp] = s + b2[warp];
    }
}

// ------------------------- launch ----------------------------------------
extern "C" void kernel_launch(void* const* d_in, const int* in_sizes, int n_in,
                              void* d_out, int out_size) {
    const float* x      = (const float*)d_in[0];
    const float* adj    = (const float*)d_in[1];
    const float* h0     = (const float*)d_in[3];
    const float* conv_w = (const float*)d_in[4];
    const float* conv_b = (const float*)d_in[5];
    const float* w_ih   = (const float*)d_in[6];
    const float* w_hh   = (const float*)d_in[7];
    const float* b_ih   = (const float*)d_in[8];
    const float* b_hh   = (const float*)d_in[9];
    const float* cls_w1 = (const float*)d_in[10];
    const float* cls_b1 = (const float*)d_in[11];
    const float* cls_w2 = (const float*)d_in[12];
    const float* cls_b2 = (const float*)d_in[13];
    float* out = (float*)d_out;

    const int REPR_SMEM = (128 * 129 + 32 * 132 + 32 * 132 + 12 * 128) * 4;  // 105984
    const int GX_SMEM   = 4 * (128 + 128) * 72 * 2;                          // 147456
    const int PS_SMEM   = 8 * (32 + 96) * 72 * 2 + 32 * 100 * 4;             // 160256
    cudaFuncSetAttribute(repr_kernel, cudaFuncAttributeMaxDynamicSharedMemorySize, REPR_SMEM);
    cudaFuncSetAttribute(gemm_gx_kernel, cudaFuncAttributeMaxDynamicSharedMemorySize, GX_SMEM);
    cudaFuncSetAttribute(gru_persistent_kernel, cudaFuncAttributeMaxDynamicSharedMemorySize, PS_SMEM);

    convert_weights_kernel<<<2048, 256>>>((const float4*)w_ih, (const float4*)w_hh);
    support_kernel<<<1, 128>>>(adj);
    repr_kernel<<<NR, 256, REPR_SMEM>>>(x, conv_w, conv_b, out);
    h_init_kernel<<<512, 256>>>(h0);

    gemm_gx_kernel<<<dim3(25, 96), 256, GX_SMEM>>>(b_ih);

    gru_persistent_kernel<<<NBLK, 256, PS_SMEM>>>(h0, b_hh, out);

    classifier_kernel<<<NB, 256>>>(cls_w1, cls_b1, cls_w2, cls_b2, out);
}

// round 8
// speedup vs baseline: 1.1214x; 1.0609x over previous
#include <cuda_runtime.h>
#include <cuda_fp16.h>
#include <cstdint>
#include <math.h>

// Problem dims
#define NB   32
#define NI   12
#define NVV  128
#define NHD  32
#define NTT  100
#define NHH  4096
#define NH3  12288
#define NR   3200
#define NBLK 128

// d_out region offsets (floats)
static const long OUT_STATES = 13107200L;
static const long OUT_HENC   = 26214400L;
static const long OUT_CLS    = 26345472L;

// ------------------------- scratch -----------------------------------------
__device__ float    gSupport[NVV * NVV];
__device__ __half   gReprH[(long)NR * NHH];
__device__ __half   gWih[(long)NH3 * NHH];
__device__ __half   gWhh[(long)NH3 * NHH];
__device__ float    gGx[(long)NR * NH3];
__device__ __half   gHh[2][NB * NHH];
__device__ unsigned gBarCnt;
__device__ unsigned gBarPhase;

// ------------------------- asm helpers -------------------------------------
__device__ __forceinline__ void cp_async16(void* smem, const void* gmem) {
    uint32_t s = (uint32_t)__cvta_generic_to_shared(smem);
    asm volatile("cp.async.cg.shared.global [%0], [%1], 16;\n" :: "r"(s), "l"(gmem));
}
__device__ __forceinline__ void cp_commit() {
    asm volatile("cp.async.commit_group;\n");
}
template <int N>
__device__ __forceinline__ void cp_wait() {
    asm volatile("cp.async.wait_group %0;\n" :: "n"(N));
}
__device__ __forceinline__ uint32_t smem_u32(const void* p) {
    return (uint32_t)__cvta_generic_to_shared(p);
}
__device__ __forceinline__ void ldsm_x4(uint32_t& r0, uint32_t& r1, uint32_t& r2,
                                        uint32_t& r3, uint32_t addr) {
    asm volatile("ldmatrix.sync.aligned.m8n8.x4.shared.b16 {%0,%1,%2,%3}, [%4];\n"
                 : "=r"(r0), "=r"(r1), "=r"(r2), "=r"(r3) : "r"(addr));
}
__device__ __forceinline__ void ldsm_x2(uint32_t& r0, uint32_t& r1, uint32_t addr) {
    asm volatile("ldmatrix.sync.aligned.m8n8.x2.shared.b16 {%0,%1}, [%2];\n"
                 : "=r"(r0), "=r"(r1) : "r"(addr));
}
__device__ __forceinline__ void mma_m16n8k16(float* d, const uint32_t* a,
                                             uint32_t b0, uint32_t b1) {
    asm volatile(
        "mma.sync.aligned.m16n8k16.row.col.f32.f16.f16.f32 "
        "{%0,%1,%2,%3}, {%4,%5,%6,%7}, {%8,%9}, {%0,%1,%2,%3};\n"
        : "+f"(d[0]), "+f"(d[1]), "+f"(d[2]), "+f"(d[3])
        : "r"(a[0]), "r"(a[1]), "r"(a[2]), "r"(a[3]), "r"(b0), "r"(b1));
}

// ------------------------- weight conversion --------------------------------
__global__ void convert_weights_kernel(const float4* __restrict__ wih4,
                                       const float4* __restrict__ whh4) {
    long n4 = (long)NH3 * NHH / 4;
    long stride = (long)gridDim.x * blockDim.x;
    __half2* wih_o = (__half2*)gWih;
    __half2* whh_o = (__half2*)gWhh;
    for (long i = (long)blockIdx.x * blockDim.x + threadIdx.x; i < n4; i += stride) {
        float4 a = wih4[i];
        wih_o[2 * i]     = __floats2half2_rn(a.x, a.y);
        wih_o[2 * i + 1] = __floats2half2_rn(a.z, a.w);
        float4 b = whh4[i];
        whh_o[2 * i]     = __floats2half2_rn(b.x, b.y);
        whh_o[2 * i + 1] = __floats2half2_rn(b.z, b.w);
    }
}

// ------------------------- support -----------------------------------------
__global__ void support_kernel(const float* __restrict__ adj) {
    int w = threadIdx.x;
    float s = 0.f;
    for (int v = 0; v < NVV; v++) s += adj[w * NVV + v];
    float inv = 1.f / (s + 1e-6f);
    for (int v = 0; v < NVV; v++) gSupport[w * NVV + v] = adj[w * NVV + v] * inv;
}

// ------------------------- repr --------------------------------------------
__global__ void repr_kernel(const float* __restrict__ x,
                            const float* __restrict__ conv_w,
                            const float* __restrict__ conv_b,
                            float* __restrict__ d_out) {
    extern __shared__ float sm[];
    float* supT = sm;
    float* bufA = supT + 128 * 129;
    float* bufB = bufA + 32 * 132;
    float* xs   = bufB + 32 * 132;

    int r = blockIdx.x;
    int t = r >> 5;
    int b = r & 31;
    int tid = threadIdx.x;

    for (int idx = tid; idx < NI * NVV; idx += 256) {
        int i = idx >> 7, v = idx & 127;
        xs[idx] = x[(((long)b * NI + i) * NVV + v) * NTT + t];
    }
    for (int idx = tid; idx < NVV * NVV; idx += 256) {
        int w = idx >> 7, v = idx & 127;
        supT[v * 129 + w] = gSupport[idx];
    }
    __syncthreads();

    for (int idx = tid; idx < NHD * NVV; idx += 256) {
        int h = idx >> 7, v = idx & 127;
        float a = conv_b[h];
#pragma unroll
        for (int i = 0; i < NI; i++) a += conv_w[h * NI + i] * xs[i * NVV + v];
        bufA[h * 132 + v] = a;
    }
    __syncthreads();

    int w0 = tid & 31;
    int h0 = tid >> 5;

    float acc1[4][4];
#pragma unroll
    for (int i = 0; i < 4; i++)
#pragma unroll
        for (int j = 0; j < 4; j++) acc1[i][j] = 0.f;
    for (int v = 0; v < NVV; v++) {
        float a[4], s[4];
#pragma unroll
        for (int i = 0; i < 4; i++) a[i] = bufA[(h0 + 8 * i) * 132 + v];
#pragma unroll
        for (int j = 0; j < 4; j++) s[j] = supT[v * 129 + w0 + 32 * j];
#pragma unroll
        for (int i = 0; i < 4; i++)
#pragma unroll
            for (int j = 0; j < 4; j++) acc1[i][j] += a[i] * s[j];
    }
    __syncthreads();
#pragma unroll
    for (int i = 0; i < 4; i++)
#pragma unroll
        for (int j = 0; j < 4; j++) bufB[(h0 + 8 * i) * 132 + w0 + 32 * j] = acc1[i][j];
    __syncthreads();

    float acc2[4][4];
#pragma unroll
    for (int i = 0; i < 4; i++)
#pragma unroll
        for (int j = 0; j < 4; j++) acc2[i][j] = 0.f;
    for (int v = 0; v < NVV; v++) {
        float a[4], s[4];
#pragma unroll
        for (int i = 0; i < 4; i++) a[i] = bufB[(h0 + 8 * i) * 132 + v];
#pragma unroll
        for (int j = 0; j < 4; j++) s[j] = supT[v * 129 + w0 + 32 * j];
#pragma unroll
        for (int i = 0; i < 4; i++)
#pragma unroll
            for (int j = 0; j < 4; j++) acc2[i][j] += a[i] * s[j];
    }

#pragma unroll
    for (int i = 0; i < 4; i++) {
#pragma unroll
        for (int j = 0; j < 4; j++) {
            int h = h0 + 8 * i, w = w0 + 32 * j;
            int n = h * NVV + w;
            float val = acc2[i][j];
            d_out[(long)b * (NHH * NTT) + (long)n * NTT + t] = val;
            gReprH[(long)r * NHH + n] = __float2half(val);
        }
    }
}

// ------------------------- pipelined gx GEMM (ST=4, ldmatrix) --------------
__global__ void __launch_bounds__(256) gemm_gx_kernel(const float* __restrict__ bias) {
    constexpr int BM = 128, BN = 128, BK = 64, ST = 4, LD = 72;
    extern __shared__ __half smh[];
    __half* As = smh;
    __half* Ws = smh + ST * BM * LD;

    int tid = threadIdx.x;
    int warp = tid >> 5, lane = tid & 31;
    int g = lane >> 2, ti = lane & 3;
    int wm = warp & 1, wn = warp >> 1;

    long rowA0 = (long)blockIdx.x * BM;   // M-tile (25)
    long rowW0 = (long)blockIdx.y * BN;   // N-tile (96)

    const __half* A = gReprH;
    const __half* W = gWih;

    int ldrow = tid >> 3, ldseg = tid & 7;

    // ldmatrix per-lane offsets (in halves, within a stage buffer)
    // A (x4, per mt): row = wm*64 + mt*16 + (lane&15), kcol = (lane>>4)*8
    uint32_t aoff[4];
#pragma unroll
    for (int mt = 0; mt < 4; mt++)
        aoff[mt] = (wm * 64 + mt * 16 + (lane & 15)) * LD + (lane >> 4) * 8;
    // W (x4, per pair): row = wn*32 + pair*16 + ((lane>>4)&1)*8 + (lane&7),
    //                   kcol = ((lane>>3)&1)*8
    uint32_t woff[2];
#pragma unroll
    for (int pr = 0; pr < 2; pr++)
        woff[pr] = (wn * 32 + pr * 16 + ((lane >> 4) & 1) * 8 + (lane & 7)) * LD
                   + ((lane >> 3) & 1) * 8;

    uint32_t As_base = smem_u32(As);
    uint32_t Ws_base = smem_u32(Ws);

#pragma unroll
    for (int s = 0; s < ST - 1; s++) {
        int k0 = s * BK;
#pragma unroll
        for (int i = 0; i < 4; i++) {
            int row = ldrow + i * 32;
            cp_async16(As + (s * BM + row) * LD + ldseg * 8,
                       A + (rowA0 + row) * (long)NHH + k0 + ldseg * 8);
        }
#pragma unroll
        for (int i = 0; i < 4; i++) {
            int row = ldrow + i * 32;
            cp_async16(Ws + (s * BN + row) * LD + ldseg * 8,
                       W + (rowW0 + row) * (long)NHH + k0 + ldseg * 8);
        }
        cp_commit();
    }

    float acc[4][4][4];
#pragma unroll
    for (int mt = 0; mt < 4; mt++)
#pragma unroll
        for (int nt = 0; nt < 4; nt++)
#pragma unroll
            for (int q = 0; q < 4; q++) acc[mt][nt][q] = 0.f;

    const int KT = NHH / BK;
    for (int kt = 0; kt < KT; kt++) {
        cp_wait<ST - 2>();
        __syncthreads();
        if (kt + ST - 1 < KT) {
            int s = (kt + ST - 1) % ST;
            int k0 = (kt + ST - 1) * BK;
#pragma unroll
            for (int i = 0; i < 4; i++) {
                int row = ldrow + i * 32;
                cp_async16(As + (s * BM + row) * LD + ldseg * 8,
                           A + (rowA0 + row) * (long)NHH + k0 + ldseg * 8);
            }
#pragma unroll
            for (int i = 0; i < 4; i++) {
                int row = ldrow + i * 32;
                cp_async16(Ws + (s * BN + row) * LD + ldseg * 8,
                           W + (rowW0 + row) * (long)NHH + k0 + ldseg * 8);
            }
        }
        cp_commit();  // every iter (tail alignment)

        uint32_t Ab = As_base + (uint32_t)((kt % ST) * BM * LD) * 2;
        uint32_t Wb = Ws_base + (uint32_t)((kt % ST) * BN * LD) * 2;

#pragma unroll
        for (int kk = 0; kk < BK; kk += 16) {
            uint32_t af[4][4];
#pragma unroll
            for (int mt = 0; mt < 4; mt++)
                ldsm_x4(af[mt][0], af[mt][1], af[mt][2], af[mt][3],
                        Ab + (aoff[mt] + kk) * 2);
            uint32_t bf[4][2];
#pragma unroll
            for (int pr = 0; pr < 2; pr++)
                ldsm_x4(bf[2 * pr][0], bf[2 * pr][1], bf[2 * pr + 1][0], bf[2 * pr + 1][1],
                        Wb + (woff[pr] + kk) * 2);
#pragma unroll
            for (int nt = 0; nt < 4; nt++)
#pragma unroll
                for (int mt = 0; mt < 4; mt++)
                    mma_m16n8k16(acc[mt][nt], af[mt], bf[nt][0], bf[nt][1]);
        }
    }

    float* C = gGx;
#pragma unroll
    for (int mt = 0; mt < 4; mt++) {
        long row = rowA0 + wm * 64 + mt * 16 + g;
#pragma unroll
        for (int nt = 0; nt < 4; nt++) {
            long col = rowW0 + wn * 32 + nt * 8 + 2 * ti;
            float bv0 = bias[col], bv1 = bias[col + 1];
            C[row * NH3 + col]           = acc[mt][nt][0] + bv0;
            C[row * NH3 + col + 1]       = acc[mt][nt][1] + bv1;
            C[(row + 8) * NH3 + col]     = acc[mt][nt][2] + bv0;
            C[(row + 8) * NH3 + col + 1] = acc[mt][nt][3] + bv1;
        }
    }
}

// ------------------------- h init -------------------------------------------
__global__ void h_init_kernel(const float* __restrict__ h0) {
    int idx = blockIdx.x * blockDim.x + threadIdx.x;
    gHh[0][idx] = __float2half(h0[idx & (NHH - 1)]);
}

// ------------------------- persistent GRU (ST=8, ldmatrix) ------------------
__global__ void __launch_bounds__(256) gru_persistent_kernel(
    const float* __restrict__ h0,
    const float* __restrict__ b_hh,
    float* __restrict__ d_out) {
    constexpr int BK = 64, ST = 8, LD = 72, WR = 96, AR = 32;
    extern __shared__ char smraw[];
    __half* As   = (__half*)smraw;                // ST * 32 * LD
    __half* Ws   = As + ST * AR * LD;             // ST * 96 * LD
    float*  gh_s = (float*)(Ws + ST * WR * LD);   // 32 * 100

    int tid = threadIdx.x;
    int warp = tid >> 5, lane = tid & 31;
    int g = lane >> 2, ti = lane & 3;
    int wm = warp & 1, wn = warp >> 1;
    int n0 = blockIdx.x * 32;

    int ldrow = tid >> 3, ldseg = tid & 7;

    const __half* wptr[3];
#pragma unroll
    for (int i = 0; i < 3; i++) {
        int lr = ldrow + i * 32;
        long wr = (long)(lr >> 5) * NHH + n0 + (lr & 31);
        wptr[i] = gWhh + wr * (long)NHH + ldseg * 8;
    }

    // ldmatrix per-lane offsets (halves, within stage buffer)
    // A x4: row = wm*16 + (lane&15), kcol = (lane>>4)*8
    uint32_t aoff = (wm * 16 + (lane & 15)) * LD + (lane >> 4) * 8;
    // W x4 pair (nt0,nt1): row = wn*24 + ((lane>>4)&1)*8 + (lane&7)
    uint32_t woff4 = (wn * 24 + ((lane >> 4) & 1) * 8 + (lane & 7)) * LD
                     + ((lane >> 3) & 1) * 8;
    // W x2 (nt2): row = wn*24 + 16 + (lane&7), lanes 0-15 used
    uint32_t woff2 = (wn * 24 + 16 + (lane & 7)) * LD + ((lane >> 3) & 1) * 8;

    uint32_t As_base = smem_u32(As);
    uint32_t Ws_base = smem_u32(Ws);

    int pb[4], pn[4];
    float hreg[4], bhr[4], bhz[4], bhn[4];
#pragma unroll
    for (int i = 0; i < 4; i++) {
        int idx = tid + i * 256;
        pb[i] = idx >> 5;
        pn[i] = n0 + (idx & 31);
        hreg[i] = h0[pn[i]];
        bhr[i] = b_hh[pn[i]];
        bhz[i] = b_hh[NHH + pn[i]];
        bhn[i] = b_hh[2 * NHH + pn[i]];
    }

    unsigned barBase = *(volatile unsigned*)&gBarPhase;

    // prologue: ST-1 W groups, ST-1 A groups
#pragma unroll
    for (int s = 0; s < ST - 1; s++) {
        int k0 = s * BK;
#pragma unroll
        for (int i = 0; i < 3; i++) {
            int lr = ldrow + i * 32;
            cp_async16(Ws + (s * WR + lr) * LD + ldseg * 8, wptr[i] + k0);
        }
        cp_commit();
    }
    {
        const __half* ap0 = gHh[0] + ldrow * NHH + ldseg * 8;
#pragma unroll
        for (int s = 0; s < ST - 1; s++) {
            cp_async16(As + (s * AR + ldrow) * LD + ldseg * 8, ap0 + s * BK);
            cp_commit();
        }
    }

    const int KT = NHH / BK;
    for (int t = 0; t < NTT; t++) {
        const __half* aptr = gHh[t & 1] + ldrow * NHH + ldseg * 8;
        __half* Aout = gHh[(t + 1) & 1];

        float pxr[4], pxz[4], pxn[4];
#pragma unroll
        for (int i = 0; i < 4; i++) {
            long gxr = ((long)(t * NB + pb[i])) * NH3 + pn[i];
            pxr[i] = gGx[gxr];
            pxz[i] = gGx[gxr + NHH];
            pxn[i] = gGx[gxr + 2 * NHH];
        }

        float acc[3][4];
#pragma unroll
        for (int nt = 0; nt < 3; nt++)
#pragma unroll
            for (int q = 0; q < 4; q++) acc[nt][q] = 0.f;

        for (int kt = 0; kt < KT; kt++) {
            cp_wait<ST - 2>();
            __syncthreads();
            if (kt + ST - 1 < KT) {
                int s = (kt + ST - 1) & (ST - 1);
                int k0 = (kt + ST - 1) * BK;
                cp_async16(As + (s * AR + ldrow) * LD + ldseg * 8, aptr + k0);
#pragma unroll
                for (int i = 0; i < 3; i++) {
                    int lr = ldrow + i * 32;
                    cp_async16(Ws + (s * WR + lr) * LD + ldseg * 8, wptr[i] + k0);
                }
            }
            cp_commit();

            uint32_t Ab = As_base + (uint32_t)((kt & (ST - 1)) * AR * LD) * 2;
            uint32_t Wb = Ws_base + (uint32_t)((kt & (ST - 1)) * WR * LD) * 2;

#pragma unroll
            for (int kk = 0; kk < BK; kk += 16) {
                uint32_t af[4];
                ldsm_x4(af[0], af[1], af[2], af[3], Ab + (aoff + kk) * 2);
                uint32_t b00, b01, b10, b11, b20, b21;
                ldsm_x4(b00, b01, b10, b11, Wb + (woff4 + kk) * 2);
                ldsm_x2(b20, b21, Wb + (woff2 + kk) * 2);
                mma_m16n8k16(acc[0], af, b00, b01);
                mma_m16n8k16(acc[1], af, b10, b11);
                mma_m16n8k16(acc[2], af, b20, b21);
            }
        }

        // gh -> smem
#pragma unroll
        for (int nt = 0; nt < 3; nt++) {
            int c = (wn * 3 + nt) * 8 + 2 * ti;
            int m = wm * 16 + g;
            gh_s[m * 100 + c]           = acc[nt][0];
            gh_s[m * 100 + c + 1]       = acc[nt][1];
            gh_s[(m + 8) * 100 + c]     = acc[nt][2];
            gh_s[(m + 8) * 100 + c + 1] = acc[nt][3];
        }
        __syncthreads();

#pragma unroll
        for (int i = 0; i < 4; i++) {
            int b = pb[i], nl = pn[i] - n0, n = pn[i];

            float hr = gh_s[b * 100 + nl]      + bhr[i];
            float hz = gh_s[b * 100 + 32 + nl] + bhz[i];
            float hn = gh_s[b * 100 + 64 + nl] + bhn[i];

            float r = 1.f / (1.f + expf(-(pxr[i] + hr)));
            float z = 1.f / (1.f + expf(-(pxz[i] + hz)));
            float nn = tanhf(pxn[i] + r * hn);
            float hnew = (1.f - z) * nn + z * hreg[i];
            hreg[i] = hnew;

            Aout[b * NHH + n] = __float2half(hnew);
            d_out[OUT_STATES + (long)b * (NHH * NTT) + (long)n * NTT + t] = hnew;
            if (t == NTT - 1) d_out[OUT_HENC + b * NHH + n] = hnew;
        }

        if (t < NTT - 1) {
#pragma unroll
            for (int s = 0; s < ST - 1; s++) {
                int k0 = s * BK;
#pragma unroll
                for (int i = 0; i < 3; i++) {
                    int lr = ldrow + i * 32;
                    cp_async16(Ws + (s * WR + lr) * LD + ldseg * 8, wptr[i] + k0);
                }
                cp_commit();
            }

            __syncthreads();
            if (tid == 0) {
                __threadfence();
                unsigned arrived = atomicAdd(&gBarCnt, 1u);
                unsigned target = barBase + (unsigned)(t + 1);
                if (arrived == NBLK - 1) {
                    gBarCnt = 0;
                    __threadfence();
                    atomicExch(&gBarPhase, target);
                } else {
                    while ((int)(atomicAdd(&gBarPhase, 0u) - target) < 0) {
                        __nanosleep(32);
                    }
                }
            }
            __syncthreads();

            const __half* ap2 = gHh[(t + 1) & 1] + ldrow * NHH + ldseg * 8;
#pragma unroll
            for (int s = 0; s < ST - 1; s++) {
                cp_async16(As + (s * AR + ldrow) * LD + ldseg * 8, ap2 + s * BK);
                cp_commit();
            }
        }
    }
    cp_wait<0>();
}

// ------------------------- classifier ---------------------------------------
__global__ void classifier_kernel(const float* __restrict__ w1, const float* __restrict__ b1,
                                  const float* __restrict__ w2, const float* __restrict__ b2,
                                  float* __restrict__ d_out) {
    __shared__ float hid[300];
    int b = blockIdx.x;
    int tid = threadIdx.x, warp = tid >> 5, lane = tid & 31;
    const float* hb = d_out + OUT_HENC + (long)b * NHH;

    for (int j = warp; j < 300; j += 8) {
        float s = 0.f;
        for (int k = lane; k < NHH; k += 32) s += hb[k] * w1[(long)j * NHH + k];
#pragma unroll
        for (int off = 16; off; off >>= 1) s += __shfl_xor_sync(0xffffffffu, s, off);
        if (lane == 0) hid[j] = fmaxf(s + b1[j], 0.f);
    }
    __syncthreads();
    if (warp < 2) {
        float s = 0.f;
        for (int j = lane; j < 300; j += 32) s += hid[j] * w2[warp * 300 + j];
#pragma unroll
        for (int off = 16; off; off >>= 1) s += __shfl_xor_sync(0xffffffffu, s, off);
        if (lane == 0) d_out[OUT_CLS + b * 2 + warp] = s + b2[warp];
    }
}

// ------------------------- launch --------------------------------------------
extern "C" void kernel_launch(void* const* d_in, const int* in_sizes, int n_in,
                              void* d_out, int out_size) {
    const float* x      = (const float*)d_in[0];
    const float* adj    = (const float*)d_in[1];
    const float* h0     = (const float*)d_in[3];
    const float* conv_w = (const float*)d_in[4];
    const float* conv_b = (const float*)d_in[5];
    const float* w_ih   = (const float*)d_in[6];
    const float* w_hh   = (const float*)d_in[7];
    const float* b_ih   = (const float*)d_in[8];
    const float* b_hh   = (const float*)d_in[9];
    const float* cls_w1 = (const float*)d_in[10];
    const float* cls_b1 = (const float*)d_in[11];
    const float* cls_w2 = (const float*)d_in[12];
    const float* cls_b2 = (const float*)d_in[13];
    float* out = (float*)d_out;

    const int REPR_SMEM = (128 * 129 + 32 * 132 + 32 * 132 + 12 * 128) * 4;  // 105984
    const int GX_SMEM   = 4 * (128 + 128) * 72 * 2;                          // 147456
    const int PS_SMEM   = 8 * (32 + 96) * 72 * 2 + 32 * 100 * 4;             // 160256
    cudaFuncSetAttribute(repr_kernel, cudaFuncAttributeMaxDynamicSharedMemorySize, REPR_SMEM);
    cudaFuncSetAttribute(gemm_gx_kernel, cudaFuncAttributeMaxDynamicSharedMemorySize, GX_SMEM);
    cudaFuncSetAttribute(gru_persistent_kernel, cudaFuncAttributeMaxDynamicSharedMemorySize, PS_SMEM);

    // Launch order puts gemm_gx in the ncu capture slot (slot 4).
    convert_weights_kernel<<<2048, 256>>>((const float4*)w_ih, (const float4*)w_hh);
    support_kernel<<<1, 128>>>(adj);
    repr_kernel<<<NR, 256, REPR_SMEM>>>(x, conv_w, conv_b, out);

    gemm_gx_kernel<<<dim3(25, 96), 256, GX_SMEM>>>(b_ih);

    h_init_kernel<<<512, 256>>>(h0);
    gru_persistent_kernel<<<NBLK, 256, PS_SMEM>>>(h0, b_hh, out);
    classifier_kernel<<<NB, 256>>>(cls_w1, cls_b1, cls_w2, cls_b2, out);
}

// round 9
// speedup vs baseline: 1.1923x; 1.0633x over previous
#include <cuda_runtime.h>
#include <cuda_fp16.h>
#include <cstdint>
#include <math.h>

// Problem dims
#define NB   32
#define NI   12
#define NVV  128
#define NHD  32
#define NTT  100
#define NHH  4096
#define NH3  12288
#define NR   3200
#define NBLK 128

// d_out region offsets (floats)
static const long OUT_STATES = 13107200L;
static const long OUT_HENC   = 26214400L;
static const long OUT_CLS    = 26345472L;

// ------------------------- scratch -----------------------------------------
__device__ float    gSupport[NVV * NVV];
__device__ __half   gReprH[(long)NR * NHH];
__device__ __half   gWih[(long)NH3 * NHH];
__device__ __half   gWhh[(long)NH3 * NHH];
__device__ float    gGx[(long)NR * NH3];
__device__ __half   gHh[2][NB * NHH];
__device__ unsigned gBarCnt;
__device__ unsigned gBarPhase;

// ------------------------- asm helpers -------------------------------------
__device__ __forceinline__ void cp_async16(void* smem, const void* gmem) {
    uint32_t s = (uint32_t)__cvta_generic_to_shared(smem);
    asm volatile("cp.async.cg.shared.global [%0], [%1], 16;\n" :: "r"(s), "l"(gmem));
}
__device__ __forceinline__ void cp_commit() {
    asm volatile("cp.async.commit_group;\n");
}
template <int N>
__device__ __forceinline__ void cp_wait() {
    asm volatile("cp.async.wait_group %0;\n" :: "n"(N));
}
__device__ __forceinline__ uint32_t smem_u32(const void* p) {
    return (uint32_t)__cvta_generic_to_shared(p);
}
__device__ __forceinline__ void ldsm_x4(uint32_t& r0, uint32_t& r1, uint32_t& r2,
                                        uint32_t& r3, uint32_t addr) {
    asm volatile("ldmatrix.sync.aligned.m8n8.x4.shared.b16 {%0,%1,%2,%3}, [%4];\n"
                 : "=r"(r0), "=r"(r1), "=r"(r2), "=r"(r3) : "r"(addr));
}
__device__ __forceinline__ void ldsm_x2(uint32_t& r0, uint32_t& r1, uint32_t addr) {
    asm volatile("ldmatrix.sync.aligned.m8n8.x2.shared.b16 {%0,%1}, [%2];\n"
                 : "=r"(r0), "=r"(r1) : "r"(addr));
}
__device__ __forceinline__ void mma_m16n8k16(float* d, const uint32_t* a,
                                             uint32_t b0, uint32_t b1) {
    asm volatile(
        "mma.sync.aligned.m16n8k16.row.col.f32.f16.f16.f32 "
        "{%0,%1,%2,%3}, {%4,%5,%6,%7}, {%8,%9}, {%0,%1,%2,%3};\n"
        : "+f"(d[0]), "+f"(d[1]), "+f"(d[2]), "+f"(d[3])
        : "r"(a[0]), "r"(a[1]), "r"(a[2]), "r"(a[3]), "r"(b0), "r"(b1));
}

// ------------------------- init: weights + support + h0 ---------------------
__global__ void init_kernel(const float4* __restrict__ wih4,
                            const float4* __restrict__ whh4,
                            const float* __restrict__ adj,
                            const float* __restrict__ h0) {
    long gid = (long)blockIdx.x * blockDim.x + threadIdx.x;

    // support (block 0, 128 threads)
    if (blockIdx.x == 0 && threadIdx.x < NVV) {
        int w = threadIdx.x;
        float s = 0.f;
        for (int v = 0; v < NVV; v++) s += adj[w * NVV + v];
        float inv = 1.f / (s + 1e-6f);
        for (int v = 0; v < NVV; v++) gSupport[w * NVV + v] = adj[w * NVV + v] * inv;
    }

    // h init (first 512 blocks' worth)
    if (gid < (long)NB * NHH) {
        gHh[0][gid] = __float2half(h0[gid & (NHH - 1)]);
    }

    // weight conversion (grid-stride)
    long n4 = (long)NH3 * NHH / 4;
    long stride = (long)gridDim.x * blockDim.x;
    __half2* wih_o = (__half2*)gWih;
    __half2* whh_o = (__half2*)gWhh;
    for (long i = gid; i < n4; i += stride) {
        float4 a = wih4[i];
        wih_o[2 * i]     = __floats2half2_rn(a.x, a.y);
        wih_o[2 * i + 1] = __floats2half2_rn(a.z, a.w);
        float4 b = whh4[i];
        whh_o[2 * i]     = __floats2half2_rn(b.x, b.y);
        whh_o[2 * i + 1] = __floats2half2_rn(b.z, b.w);
    }
}

// ------------------------- repr --------------------------------------------
__global__ void repr_kernel(const float* __restrict__ x,
                            const float* __restrict__ conv_w,
                            const float* __restrict__ conv_b,
                            float* __restrict__ d_out) {
    extern __shared__ float sm[];
    float* supT = sm;
    float* bufA = supT + 128 * 129;
    float* bufB = bufA + 32 * 132;
    float* xs   = bufB + 32 * 132;

    int r = blockIdx.x;
    int t = r >> 5;
    int b = r & 31;
    int tid = threadIdx.x;

    for (int idx = tid; idx < NI * NVV; idx += 256) {
        int i = idx >> 7, v = idx & 127;
        xs[idx] = x[(((long)b * NI + i) * NVV + v) * NTT + t];
    }
    for (int idx = tid; idx < NVV * NVV; idx += 256) {
        int w = idx >> 7, v = idx & 127;
        supT[v * 129 + w] = gSupport[idx];
    }
    __syncthreads();

    for (int idx = tid; idx < NHD * NVV; idx += 256) {
        int h = idx >> 7, v = idx & 127;
        float a = conv_b[h];
#pragma unroll
        for (int i = 0; i < NI; i++) a += conv_w[h * NI + i] * xs[i * NVV + v];
        bufA[h * 132 + v] = a;
    }
    __syncthreads();

    int w0 = tid & 31;
    int h0 = tid >> 5;

    float acc1[4][4];
#pragma unroll
    for (int i = 0; i < 4; i++)
#pragma unroll
        for (int j = 0; j < 4; j++) acc1[i][j] = 0.f;
    for (int v = 0; v < NVV; v++) {
        float a[4], s[4];
#pragma unroll
        for (int i = 0; i < 4; i++) a[i] = bufA[(h0 + 8 * i) * 132 + v];
#pragma unroll
        for (int j = 0; j < 4; j++) s[j] = supT[v * 129 + w0 + 32 * j];
#pragma unroll
        for (int i = 0; i < 4; i++)
#pragma unroll
            for (int j = 0; j < 4; j++) acc1[i][j] += a[i] * s[j];
    }
    __syncthreads();
#pragma unroll
    for (int i = 0; i < 4; i++)
#pragma unroll
        for (int j = 0; j < 4; j++) bufB[(h0 + 8 * i) * 132 + w0 + 32 * j] = acc1[i][j];
    __syncthreads();

    float acc2[4][4];
#pragma unroll
    for (int i = 0; i < 4; i++)
#pragma unroll
        for (int j = 0; j < 4; j++) acc2[i][j] = 0.f;
    for (int v = 0; v < NVV; v++) {
        float a[4], s[4];
#pragma unroll
        for (int i = 0; i < 4; i++) a[i] = bufB[(h0 + 8 * i) * 132 + v];
#pragma unroll
        for (int j = 0; j < 4; j++) s[j] = supT[v * 129 + w0 + 32 * j];
#pragma unroll
        for (int i = 0; i < 4; i++)
#pragma unroll
            for (int j = 0; j < 4; j++) acc2[i][j] += a[i] * s[j];
    }

#pragma unroll
    for (int i = 0; i < 4; i++) {
#pragma unroll
        for (int j = 0; j < 4; j++) {
            int h = h0 + 8 * i, w = w0 + 32 * j;
            int n = h * NVV + w;
            float val = acc2[i][j];
            d_out[(long)b * (NHH * NTT) + (long)n * NTT + t] = val;
            gReprH[(long)r * NHH + n] = __float2half(val);
        }
    }
}

// ------------------------- pipelined gx GEMM (ST=3, 2 CTA/SM) --------------
__global__ void __launch_bounds__(256, 2) gemm_gx_kernel(const float* __restrict__ bias) {
    constexpr int BM = 128, BN = 128, BK = 64, ST = 3, LD = 72;
    extern __shared__ __half smh[];
    __half* As = smh;
    __half* Ws = smh + ST * BM * LD;

    int tid = threadIdx.x;
    int warp = tid >> 5, lane = tid & 31;
    int g = lane >> 2, ti = lane & 3;
    int wm = warp & 1, wn = warp >> 1;

    long rowA0 = (long)blockIdx.x * BM;   // M-tile (25)
    long rowW0 = (long)blockIdx.y * BN;   // N-tile (96)

    const __half* A = gReprH;
    const __half* W = gWih;

    int ldrow = tid >> 3, ldseg = tid & 7;

    uint32_t aoff[4];
#pragma unroll
    for (int mt = 0; mt < 4; mt++)
        aoff[mt] = (wm * 64 + mt * 16 + (lane & 15)) * LD + (lane >> 4) * 8;
    uint32_t woff[2];
#pragma unroll
    for (int pr = 0; pr < 2; pr++)
        woff[pr] = (wn * 32 + pr * 16 + ((lane >> 4) & 1) * 8 + (lane & 7)) * LD
                   + ((lane >> 3) & 1) * 8;

    uint32_t As_base = smem_u32(As);
    uint32_t Ws_base = smem_u32(Ws);

#pragma unroll
    for (int s = 0; s < ST - 1; s++) {
        int k0 = s * BK;
#pragma unroll
        for (int i = 0; i < 4; i++) {
            int row = ldrow + i * 32;
            cp_async16(As + (s * BM + row) * LD + ldseg * 8,
                       A + (rowA0 + row) * (long)NHH + k0 + ldseg * 8);
        }
#pragma unroll
        for (int i = 0; i < 4; i++) {
            int row = ldrow + i * 32;
            cp_async16(Ws + (s * BN + row) * LD + ldseg * 8,
                       W + (rowW0 + row) * (long)NHH + k0 + ldseg * 8);
        }
        cp_commit();
    }

    float acc[4][4][4];
#pragma unroll
    for (int mt = 0; mt < 4; mt++)
#pragma unroll
        for (int nt = 0; nt < 4; nt++)
#pragma unroll
            for (int q = 0; q < 4; q++) acc[mt][nt][q] = 0.f;

    const int KT = NHH / BK;
    for (int kt = 0; kt < KT; kt++) {
        cp_wait<ST - 2>();
        __syncthreads();
        if (kt + ST - 1 < KT) {
            int s = (kt + ST - 1) % ST;
            int k0 = (kt + ST - 1) * BK;
#pragma unroll
            for (int i = 0; i < 4; i++) {
                int row = ldrow + i * 32;
                cp_async16(As + (s * BM + row) * LD + ldseg * 8,
                           A + (rowA0 + row) * (long)NHH + k0 + ldseg * 8);
            }
#pragma unroll
            for (int i = 0; i < 4; i++) {
                int row = ldrow + i * 32;
                cp_async16(Ws + (s * BN + row) * LD + ldseg * 8,
                           W + (rowW0 + row) * (long)NHH + k0 + ldseg * 8);
            }
        }
        cp_commit();  // every iter (tail alignment)

        uint32_t Ab = As_base + (uint32_t)((kt % ST) * BM * LD) * 2;
        uint32_t Wb = Ws_base + (uint32_t)((kt % ST) * BN * LD) * 2;

#pragma unroll
        for (int kk = 0; kk < BK; kk += 16) {
            uint32_t af[4][4];
#pragma unroll
            for (int mt = 0; mt < 4; mt++)
                ldsm_x4(af[mt][0], af[mt][1], af[mt][2], af[mt][3],
                        Ab + (aoff[mt] + kk) * 2);
            uint32_t bf[4][2];
#pragma unroll
            for (int pr = 0; pr < 2; pr++)
                ldsm_x4(bf[2 * pr][0], bf[2 * pr][1], bf[2 * pr + 1][0], bf[2 * pr + 1][1],
                        Wb + (woff[pr] + kk) * 2);
#pragma unroll
            for (int nt = 0; nt < 4; nt++)
#pragma unroll
                for (int mt = 0; mt < 4; mt++)
                    mma_m16n8k16(acc[mt][nt], af[mt], bf[nt][0], bf[nt][1]);
        }
    }

    float* C = gGx;
#pragma unroll
    for (int mt = 0; mt < 4; mt++) {
        long row = rowA0 + wm * 64 + mt * 16 + g;
#pragma unroll
        for (int nt = 0; nt < 4; nt++) {
            long col = rowW0 + wn * 32 + nt * 8 + 2 * ti;
            float bv0 = bias[col], bv1 = bias[col + 1];
            C[row * NH3 + col]           = acc[mt][nt][0] + bv0;
            C[row * NH3 + col + 1]       = acc[mt][nt][1] + bv1;
            C[(row + 8) * NH3 + col]     = acc[mt][nt][2] + bv0;
            C[(row + 8) * NH3 + col + 1] = acc[mt][nt][3] + bv1;
        }
    }
}

// ------------------------- persistent GRU (BK=128, ST=4, ldmatrix) ----------
__global__ void __launch_bounds__(256) gru_persistent_kernel(
    const float* __restrict__ h0,
    const float* __restrict__ b_hh,
    float* __restrict__ d_out) {
    constexpr int BK = 128, ST = 4, LD = 136, WR = 96, AR = 32;
    extern __shared__ char smraw[];
    __half* As   = (__half*)smraw;                // ST * 32 * LD
    __half* Ws   = As + ST * AR * LD;             // ST * 96 * LD
    float*  gh_s = (float*)(Ws + ST * WR * LD);   // 32 * 100

    int tid = threadIdx.x;
    int warp = tid >> 5, lane = tid & 31;
    int g = lane >> 2, ti = lane & 3;
    int wm = warp & 1, wn = warp >> 1;
    int n0 = blockIdx.x * 32;

    int ldrow = tid >> 4, ldseg = tid & 15;   // 16 threads per 256B row

    // W row pointers (6 per thread; rows lr = ldrow + 16j)
    const __half* wptr[6];
#pragma unroll
    for (int j = 0; j < 6; j++) {
        int lr = ldrow + j * 16;
        long wr = (long)(lr >> 5) * NHH + n0 + (lr & 31);
        wptr[j] = gWhh + wr * (long)NHH + ldseg * 8;
    }
    // A row offsets (2 per thread)
    long aoffg[2];
#pragma unroll
    for (int j = 0; j < 2; j++) aoffg[j] = (long)(ldrow + j * 16) * NHH + ldseg * 8;

    // ldmatrix per-lane offsets (halves, within stage buffer)
    uint32_t aoff = (wm * 16 + (lane & 15)) * LD + (lane >> 4) * 8;
    uint32_t woff4 = (wn * 24 + ((lane >> 4) & 1) * 8 + (lane & 7)) * LD
                     + ((lane >> 3) & 1) * 8;
    uint32_t woff2 = (wn * 24 + 16 + (lane & 7)) * LD + ((lane >> 3) & 1) * 8;

    uint32_t As_base = smem_u32(As);
    uint32_t Ws_base = smem_u32(Ws);

    int pb[4], pn[4];
    float hreg[4], bhr[4], bhz[4], bhn[4];
#pragma unroll
    for (int i = 0; i < 4; i++) {
        int idx = tid + i * 256;
        pb[i] = idx >> 5;
        pn[i] = n0 + (idx & 31);
        hreg[i] = h0[pn[i]];
        bhr[i] = b_hh[pn[i]];
        bhz[i] = b_hh[NHH + pn[i]];
        bhn[i] = b_hh[2 * NHH + pn[i]];
    }

    unsigned barBase = *(volatile unsigned*)&gBarPhase;

    // prologue: ST-1 W groups, ST-1 A groups
#pragma unroll
    for (int s = 0; s < ST - 1; s++) {
        int k0 = s * BK;
#pragma unroll
        for (int j = 0; j < 6; j++) {
            int lr = ldrow + j * 16;
            cp_async16(Ws + (s * WR + lr) * LD + ldseg * 8, wptr[j] + k0);
        }
        cp_commit();
    }
    {
        const __half* A0 = gHh[0];
#pragma unroll
        for (int s = 0; s < ST - 1; s++) {
#pragma unroll
            for (int j = 0; j < 2; j++)
                cp_async16(As + (s * AR + ldrow + j * 16) * LD + ldseg * 8,
                           A0 + aoffg[j] + s * BK);
            cp_commit();
        }
    }

    const int KT = NHH / BK;  // 32
    for (int t = 0; t < NTT; t++) {
        const __half* Ain = gHh[t & 1];
        __half* Aout = gHh[(t + 1) & 1];

        float pxr[4], pxz[4], pxn[4];
#pragma unroll
        for (int i = 0; i < 4; i++) {
            long gxr = ((long)(t * NB + pb[i])) * NH3 + pn[i];
            pxr[i] = gGx[gxr];
            pxz[i] = gGx[gxr + NHH];
            pxn[i] = gGx[gxr + 2 * NHH];
        }

        float acc[3][4];
#pragma unroll
        for (int nt = 0; nt < 3; nt++)
#pragma unroll
            for (int q = 0; q < 4; q++) acc[nt][q] = 0.f;

        for (int kt = 0; kt < KT; kt++) {
            cp_wait<ST - 2>();
            __syncthreads();
            if (kt + ST - 1 < KT) {
                int s = (kt + ST - 1) & (ST - 1);
                int k0 = (kt + ST - 1) * BK;
#pragma unroll
                for (int j = 0; j < 2; j++)
                    cp_async16(As + (s * AR + ldrow + j * 16) * LD + ldseg * 8,
                               Ain + aoffg[j] + k0);
#pragma unroll
                for (int j = 0; j < 6; j++) {
                    int lr = ldrow + j * 16;
                    cp_async16(Ws + (s * WR + lr) * LD + ldseg * 8, wptr[j] + k0);
                }
            }
            cp_commit();  // every iteration (tail alignment)

            uint32_t Ab = As_base + (uint32_t)((kt & (ST - 1)) * AR * LD) * 2;
            uint32_t Wb = Ws_base + (uint32_t)((kt & (ST - 1)) * WR * LD) * 2;

#pragma unroll
            for (int kk = 0; kk < BK; kk += 16) {
                uint32_t af[4];
                ldsm_x4(af[0], af[1], af[2], af[3], Ab + (aoff + kk) * 2);
                uint32_t b00, b01, b10, b11, b20, b21;
                ldsm_x4(b00, b01, b10, b11, Wb + (woff4 + kk) * 2);
                ldsm_x2(b20, b21, Wb + (woff2 + kk) * 2);
                mma_m16n8k16(acc[0], af, b00, b01);
                mma_m16n8k16(acc[1], af, b10, b11);
                mma_m16n8k16(acc[2], af, b20, b21);
            }
        }

        // gh -> smem
#pragma unroll
        for (int nt = 0; nt < 3; nt++) {
            int c = (wn * 3 + nt) * 8 + 2 * ti;
            int m = wm * 16 + g;
            gh_s[m * 100 + c]           = acc[nt][0];
            gh_s[m * 100 + c + 1]       = acc[nt][1];
            gh_s[(m + 8) * 100 + c]     = acc[nt][2];
            gh_s[(m + 8) * 100 + c + 1] = acc[nt][3];
        }
        __syncthreads();

#pragma unroll
        for (int i = 0; i < 4; i++) {
            int b = pb[i], nl = pn[i] - n0, n = pn[i];

            float hr = gh_s[b * 100 + nl]      + bhr[i];
            float hz = gh_s[b * 100 + 32 + nl] + bhz[i];
            float hn = gh_s[b * 100 + 64 + nl] + bhn[i];

            float r = 1.f / (1.f + expf(-(pxr[i] + hr)));
            float z = 1.f / (1.f + expf(-(pxz[i] + hz)));
            float nn = tanhf(pxn[i] + r * hn);
            float hnew = (1.f - z) * nn + z * hreg[i];
            hreg[i] = hnew;

            Aout[b * NHH + n] = __float2half(hnew);
            d_out[OUT_STATES + (long)b * (NHH * NTT) + (long)n * NTT + t] = hnew;
            if (t == NTT - 1) d_out[OUT_HENC + b * NHH + n] = hnew;
        }

        if (t < NTT - 1) {
            // next-step W stages before barrier (barrier-independent)
#pragma unroll
            for (int s = 0; s < ST - 1; s++) {
                int k0 = s * BK;
#pragma unroll
                for (int j = 0; j < 6; j++) {
                    int lr = ldrow + j * 16;
                    cp_async16(Ws + (s * WR + lr) * LD + ldseg * 8, wptr[j] + k0);
                }
                cp_commit();
            }

            // grid barrier (hidden behind W loads)
            __syncthreads();
            if (tid == 0) {
                __threadfence();
                unsigned arrived = atomicAdd(&gBarCnt, 1u);
                unsigned target = barBase + (unsigned)(t + 1);
                if (arrived == NBLK - 1) {
                    gBarCnt = 0;
                    __threadfence();
                    atomicExch(&gBarPhase, target);
                } else {
                    while ((int)(atomicAdd(&gBarPhase, 0u) - target) < 0) {
                        __nanosleep(32);
                    }
                }
            }
            __syncthreads();

            // next-step A stages (h for t+1 globally ready)
            const __half* A2 = gHh[(t + 1) & 1];
#pragma unroll
            for (int s = 0; s < ST - 1; s++) {
#pragma unroll
                for (int j = 0; j < 2; j++)
                    cp_async16(As + (s * AR + ldrow + j * 16) * LD + ldseg * 8,
                               A2 + aoffg[j] + s * BK);
                cp_commit();
            }
        }
    }
    cp_wait<0>();
}

// ------------------------- classifier ---------------------------------------
__global__ void classifier_kernel(const float* __restrict__ w1, const float* __restrict__ b1,
                                  const float* __restrict__ w2, const float* __restrict__ b2,
                                  float* __restrict__ d_out) {
    __shared__ float hid[300];
    int b = blockIdx.x;
    int tid = threadIdx.x, warp = tid >> 5, lane = tid & 31;
    const float* hb = d_out + OUT_HENC + (long)b * NHH;

    for (int j = warp; j < 300; j += 8) {
        float s = 0.f;
        for (int k = lane; k < NHH; k += 32) s += hb[k] * w1[(long)j * NHH + k];
#pragma unroll
        for (int off = 16; off; off >>= 1) s += __shfl_xor_sync(0xffffffffu, s, off);
        if (lane == 0) hid[j] = fmaxf(s + b1[j], 0.f);
    }
    __syncthreads();
    if (warp < 2) {
        float s = 0.f;
        for (int j = lane; j < 300; j += 32) s += hid[j] * w2[warp * 300 + j];
#pragma unroll
        for (int off = 16; off; off >>= 1) s += __shfl_xor_sync(0xffffffffu, s, off);
        if (lane == 0) d_out[OUT_CLS + b * 2 + warp] = s + b2[warp];
    }
}

// ------------------------- launch --------------------------------------------
extern "C" void kernel_launch(void* const* d_in, const int* in_sizes, int n_in,
                              void* d_out, int out_size) {
    const float* x      = (const float*)d_in[0];
    const float* adj    = (const float*)d_in[1];
    const float* h0     = (const float*)d_in[3];
    const float* conv_w = (const float*)d_in[4];
    const float* conv_b = (const float*)d_in[5];
    const float* w_ih   = (const float*)d_in[6];
    const float* w_hh   = (const float*)d_in[7];
    const float* b_ih   = (const float*)d_in[8];
    const float* b_hh   = (const float*)d_in[9];
    const float* cls_w1 = (const float*)d_in[10];
    const float* cls_b1 = (const float*)d_in[11];
    const float* cls_w2 = (const float*)d_in[12];
    const float* cls_b2 = (const float*)d_in[13];
    float* out = (float*)d_out;

    const int REPR_SMEM = (128 * 129 + 32 * 132 + 32 * 132 + 12 * 128) * 4;  // 105984
    const int GX_SMEM   = 3 * (128 + 128) * 72 * 2;                          // 110592
    const int PS_SMEM   = 4 * (32 + 96) * 136 * 2 + 32 * 100 * 4;            // 152064
    cudaFuncSetAttribute(repr_kernel, cudaFuncAttributeMaxDynamicSharedMemorySize, REPR_SMEM);
    cudaFuncSetAttribute(gemm_gx_kernel, cudaFuncAttributeMaxDynamicSharedMemorySize, GX_SMEM);
    cudaFuncSetAttribute(gru_persistent_kernel, cudaFuncAttributeMaxDynamicSharedMemorySize, PS_SMEM);

    // Launch order: gru_persistent at index 3 (the ncu capture slot).
    init_kernel<<<2048, 256>>>((const float4*)w_ih, (const float4*)w_hh, adj, h0);
    repr_kernel<<<NR, 256, REPR_SMEM>>>(x, conv_w, conv_b, out);
    gemm_gx_kernel<<<dim3(25, 96), 256, GX_SMEM>>>(b_ih);
    gru_persistent_kernel<<<NBLK, 256, PS_SMEM>>>(h0, b_hh, out);
    classifier_kernel<<<NB, 256>>>(cls_w1, cls_b1, cls_w2, cls_b2, out);
}

// round 10
// speedup vs baseline: 1.1929x; 1.0005x over previous
#include <cuda_runtime.h>
#include <cuda_fp16.h>
#include <cstdint>
#include <math.h>

// Problem dims
#define NB   32
#define NI   12
#define NVV  128
#define NHD  32
#define NTT  100
#define NHH  4096
#define NH3  12288
#define NR   3200
#define NBLK 128

// d_out region offsets (floats)
static const long OUT_STATES = 13107200L;
static const long OUT_HENC   = 26214400L;
static const long OUT_CLS    = 26345472L;

// ------------------------- scratch -----------------------------------------
__device__ float    gSupport[NVV * NVV];
__device__ __half   gReprH[(long)NR * NHH];
__device__ __half   gWih[(long)NH3 * NHH];
__device__ __half   gWhh[(long)NH3 * NHH];
__device__ float    gGx[(long)NR * NH3];
__device__ __half   gHh[2][NB * NHH];
__device__ unsigned gBarCnt;
__device__ unsigned gBarPhase;

// ------------------------- asm helpers -------------------------------------
__device__ __forceinline__ uint64_t mk_evict_last_policy() {
    uint64_t pol;
    asm("createpolicy.fractional.L2::evict_last.b64 %0, 1.0;" : "=l"(pol));
    return pol;
}
__device__ __forceinline__ void cp_async16(void* smem, const void* gmem) {
    uint32_t s = (uint32_t)__cvta_generic_to_shared(smem);
    asm volatile("cp.async.cg.shared.global [%0], [%1], 16;\n" :: "r"(s), "l"(gmem));
}
// cp.async with L2 cache policy (evict_last for resident weights)
__device__ __forceinline__ void cp_async16_el(void* smem, const void* gmem, uint64_t pol) {
    uint32_t s = (uint32_t)__cvta_generic_to_shared(smem);
    asm volatile("cp.async.cg.shared.global.L2::cache_hint [%0], [%1], 16, %2;\n"
                 :: "r"(s), "l"(gmem), "l"(pol));
}
__device__ __forceinline__ void cp_commit() {
    asm volatile("cp.async.commit_group;\n");
}
template <int N>
__device__ __forceinline__ void cp_wait() {
    asm volatile("cp.async.wait_group %0;\n" :: "n"(N));
}
__device__ __forceinline__ uint32_t smem_u32(const void* p) {
    return (uint32_t)__cvta_generic_to_shared(p);
}
__device__ __forceinline__ void ldsm_x4(uint32_t& r0, uint32_t& r1, uint32_t& r2,
                                        uint32_t& r3, uint32_t addr) {
    asm volatile("ldmatrix.sync.aligned.m8n8.x4.shared.b16 {%0,%1,%2,%3}, [%4];\n"
                 : "=r"(r0), "=r"(r1), "=r"(r2), "=r"(r3) : "r"(addr));
}
__device__ __forceinline__ void ldsm_x2(uint32_t& r0, uint32_t& r1, uint32_t addr) {
    asm volatile("ldmatrix.sync.aligned.m8n8.x2.shared.b16 {%0,%1}, [%2];\n"
                 : "=r"(r0), "=r"(r1) : "r"(addr));
}
__device__ __forceinline__ void mma_m16n8k16(float* d, const uint32_t* a,
                                             uint32_t b0, uint32_t b1) {
    asm volatile(
        "mma.sync.aligned.m16n8k16.row.col.f32.f16.f16.f32 "
        "{%0,%1,%2,%3}, {%4,%5,%6,%7}, {%8,%9}, {%0,%1,%2,%3};\n"
        : "+f"(d[0]), "+f"(d[1]), "+f"(d[2]), "+f"(d[3])
        : "r"(a[0]), "r"(a[1]), "r"(a[2]), "r"(a[3]), "r"(b0), "r"(b1));
}

// ------------------------- init: weights + support + h0 ---------------------
__global__ void init_kernel(const float4* __restrict__ wih4,
                            const float4* __restrict__ whh4,
                            const float* __restrict__ adj,
                            const float* __restrict__ h0) {
    long gid = (long)blockIdx.x * blockDim.x + threadIdx.x;

    if (blockIdx.x == 0 && threadIdx.x < NVV) {
        int w = threadIdx.x;
        float s = 0.f;
        for (int v = 0; v < NVV; v++) s += adj[w * NVV + v];
        float inv = 1.f / (s + 1e-6f);
        for (int v = 0; v < NVV; v++) gSupport[w * NVV + v] = adj[w * NVV + v] * inv;
    }

    if (gid < (long)NB * NHH) {
        gHh[0][gid] = __float2half(h0[gid & (NHH - 1)]);
    }

    long n4 = (long)NH3 * NHH / 4;
    long stride = (long)gridDim.x * blockDim.x;
    __half2* wih_o = (__half2*)gWih;
    __half2* whh_o = (__half2*)gWhh;
    for (long i = gid; i < n4; i += stride) {
        float4 a = wih4[i];
        wih_o[2 * i]     = __floats2half2_rn(a.x, a.y);
        wih_o[2 * i + 1] = __floats2half2_rn(a.z, a.w);
        float4 b = whh4[i];
        whh_o[2 * i]     = __floats2half2_rn(b.x, b.y);
        whh_o[2 * i + 1] = __floats2half2_rn(b.z, b.w);
    }
}

// ------------------------- repr --------------------------------------------
__global__ void repr_kernel(const float* __restrict__ x,
                            const float* __restrict__ conv_w,
                            const float* __restrict__ conv_b,
                            float* __restrict__ d_out) {
    extern __shared__ float sm[];
    float* supT = sm;
    float* bufA = supT + 128 * 129;
    float* bufB = bufA + 32 * 132;
    float* xs   = bufB + 32 * 132;

    int r = blockIdx.x;
    int t = r >> 5;
    int b = r & 31;
    int tid = threadIdx.x;

    for (int idx = tid; idx < NI * NVV; idx += 256) {
        int i = idx >> 7, v = idx & 127;
        xs[idx] = x[(((long)b * NI + i) * NVV + v) * NTT + t];
    }
    for (int idx = tid; idx < NVV * NVV; idx += 256) {
        int w = idx >> 7, v = idx & 127;
        supT[v * 129 + w] = gSupport[idx];
    }
    __syncthreads();

    for (int idx = tid; idx < NHD * NVV; idx += 256) {
        int h = idx >> 7, v = idx & 127;
        float a = conv_b[h];
#pragma unroll
        for (int i = 0; i < NI; i++) a += conv_w[h * NI + i] * xs[i * NVV + v];
        bufA[h * 132 + v] = a;
    }
    __syncthreads();

    int w0 = tid & 31;
    int h0 = tid >> 5;

    float acc1[4][4];
#pragma unroll
    for (int i = 0; i < 4; i++)
#pragma unroll
        for (int j = 0; j < 4; j++) acc1[i][j] = 0.f;
    for (int v = 0; v < NVV; v++) {
        float a[4], s[4];
#pragma unroll
        for (int i = 0; i < 4; i++) a[i] = bufA[(h0 + 8 * i) * 132 + v];
#pragma unroll
        for (int j = 0; j < 4; j++) s[j] = supT[v * 129 + w0 + 32 * j];
#pragma unroll
        for (int i = 0; i < 4; i++)
#pragma unroll
            for (int j = 0; j < 4; j++) acc1[i][j] += a[i] * s[j];
    }
    __syncthreads();
#pragma unroll
    for (int i = 0; i < 4; i++)
#pragma unroll
        for (int j = 0; j < 4; j++) bufB[(h0 + 8 * i) * 132 + w0 + 32 * j] = acc1[i][j];
    __syncthreads();

    float acc2[4][4];
#pragma unroll
    for (int i = 0; i < 4; i++)
#pragma unroll
        for (int j = 0; j < 4; j++) acc2[i][j] = 0.f;
    for (int v = 0; v < NVV; v++) {
        float a[4], s[4];
#pragma unroll
        for (int i = 0; i < 4; i++) a[i] = bufB[(h0 + 8 * i) * 132 + v];
#pragma unroll
        for (int j = 0; j < 4; j++) s[j] = supT[v * 129 + w0 + 32 * j];
#pragma unroll
        for (int i = 0; i < 4; i++)
#pragma unroll
            for (int j = 0; j < 4; j++) acc2[i][j] += a[i] * s[j];
    }

#pragma unroll
    for (int i = 0; i < 4; i++) {
#pragma unroll
        for (int j = 0; j < 4; j++) {
            int h = h0 + 8 * i, w = w0 + 32 * j;
            int n = h * NVV + w;
            float val = acc2[i][j];
            d_out[(long)b * (NHH * NTT) + (long)n * NTT + t] = val;
            gReprH[(long)r * NHH + n] = __float2half(val);
        }
    }
}

// ------------------------- pipelined gx GEMM (ST=3, 2 CTA/SM) --------------
__global__ void __launch_bounds__(256, 2) gemm_gx_kernel(const float* __restrict__ bias) {
    constexpr int BM = 128, BN = 128, BK = 64, ST = 3, LD = 72;
    extern __shared__ __half smh[];
    __half* As = smh;
    __half* Ws = smh + ST * BM * LD;

    int tid = threadIdx.x;
    int warp = tid >> 5, lane = tid & 31;
    int g = lane >> 2, ti = lane & 3;
    int wm = warp & 1, wn = warp >> 1;

    long rowA0 = (long)blockIdx.x * BM;   // M-tile (25)
    long rowW0 = (long)blockIdx.y * BN;   // N-tile (96)

    const __half* A = gReprH;
    const __half* W = gWih;

    int ldrow = tid >> 3, ldseg = tid & 7;
    uint64_t pol = mk_evict_last_policy();   // keep A (26MB, reused 96x) in L2

    uint32_t aoff[4];
#pragma unroll
    for (int mt = 0; mt < 4; mt++)
        aoff[mt] = (wm * 64 + mt * 16 + (lane & 15)) * LD + (lane >> 4) * 8;
    uint32_t woff[2];
#pragma unroll
    for (int pr = 0; pr < 2; pr++)
        woff[pr] = (wn * 32 + pr * 16 + ((lane >> 4) & 1) * 8 + (lane & 7)) * LD
                   + ((lane >> 3) & 1) * 8;

    uint32_t As_base = smem_u32(As);
    uint32_t Ws_base = smem_u32(Ws);

#pragma unroll
    for (int s = 0; s < ST - 1; s++) {
        int k0 = s * BK;
#pragma unroll
        for (int i = 0; i < 4; i++) {
            int row = ldrow + i * 32;
            cp_async16_el(As + (s * BM + row) * LD + ldseg * 8,
                          A + (rowA0 + row) * (long)NHH + k0 + ldseg * 8, pol);
        }
#pragma unroll
        for (int i = 0; i < 4; i++) {
            int row = ldrow + i * 32;
            cp_async16(Ws + (s * BN + row) * LD + ldseg * 8,
                       W + (rowW0 + row) * (long)NHH + k0 + ldseg * 8);
        }
        cp_commit();
    }

    float acc[4][4][4];
#pragma unroll
    for (int mt = 0; mt < 4; mt++)
#pragma unroll
        for (int nt = 0; nt < 4; nt++)
#pragma unroll
            for (int q = 0; q < 4; q++) acc[mt][nt][q] = 0.f;

    const int KT = NHH / BK;
    for (int kt = 0; kt < KT; kt++) {
        cp_wait<ST - 2>();
        __syncthreads();
        if (kt + ST - 1 < KT) {
            int s = (kt + ST - 1) % ST;
            int k0 = (kt + ST - 1) * BK;
#pragma unroll
            for (int i = 0; i < 4; i++) {
                int row = ldrow + i * 32;
                cp_async16_el(As + (s * BM + row) * LD + ldseg * 8,
                              A + (rowA0 + row) * (long)NHH + k0 + ldseg * 8, pol);
            }
#pragma unroll
            for (int i = 0; i < 4; i++) {
                int row = ldrow + i * 32;
                cp_async16(Ws + (s * BN + row) * LD + ldseg * 8,
                           W + (rowW0 + row) * (long)NHH + k0 + ldseg * 8);
            }
        }
        cp_commit();  // every iter (tail alignment)

        uint32_t Ab = As_base + (uint32_t)((kt % ST) * BM * LD) * 2;
        uint32_t Wb = Ws_base + (uint32_t)((kt % ST) * BN * LD) * 2;

#pragma unroll
        for (int kk = 0; kk < BK; kk += 16) {
            uint32_t af[4][4];
#pragma unroll
            for (int mt = 0; mt < 4; mt++)
                ldsm_x4(af[mt][0], af[mt][1], af[mt][2], af[mt][3],
                        Ab + (aoff[mt] + kk) * 2);
            uint32_t bf[4][2];
#pragma unroll
            for (int pr = 0; pr < 2; pr++)
                ldsm_x4(bf[2 * pr][0], bf[2 * pr][1], bf[2 * pr + 1][0], bf[2 * pr + 1][1],
                        Wb + (woff[pr] + kk) * 2);
#pragma unroll
            for (int nt = 0; nt < 4; nt++)
#pragma unroll
                for (int mt = 0; mt < 4; mt++)
                    mma_m16n8k16(acc[mt][nt], af[mt], bf[nt][0], bf[nt][1]);
        }
    }

    // epilogue: streaming stores (evict_first) so gGx doesn't churn L2
    float* C = gGx;
#pragma unroll
    for (int mt = 0; mt < 4; mt++) {
        long row = rowA0 + wm * 64 + mt * 16 + g;
#pragma unroll
        for (int nt = 0; nt < 4; nt++) {
            long col = rowW0 + wn * 32 + nt * 8 + 2 * ti;
            float bv0 = bias[col], bv1 = bias[col + 1];
            __stcs(&C[row * NH3 + col],           acc[mt][nt][0] + bv0);
            __stcs(&C[row * NH3 + col + 1],       acc[mt][nt][1] + bv1);
            __stcs(&C[(row + 8) * NH3 + col],     acc[mt][nt][2] + bv0);
            __stcs(&C[(row + 8) * NH3 + col + 1], acc[mt][nt][3] + bv1);
        }
    }
}

// ------------------------- persistent GRU (BK=128, ST=4, evict_last W) ------
__global__ void __launch_bounds__(256) gru_persistent_kernel(
    const float* __restrict__ h0,
    const float* __restrict__ b_hh,
    float* __restrict__ d_out) {
    constexpr int BK = 128, ST = 4, LD = 136, WR = 96, AR = 32;
    extern __shared__ char smraw[];
    __half* As   = (__half*)smraw;                // ST * 32 * LD
    __half* Ws   = As + ST * AR * LD;             // ST * 96 * LD
    float*  gh_s = (float*)(Ws + ST * WR * LD);   // 32 * 100

    int tid = threadIdx.x;
    int warp = tid >> 5, lane = tid & 31;
    int g = lane >> 2, ti = lane & 3;
    int wm = warp & 1, wn = warp >> 1;
    int n0 = blockIdx.x * 32;

    int ldrow = tid >> 4, ldseg = tid & 15;   // 16 threads per 256B row
    uint64_t pol = mk_evict_last_policy();    // pin W_hh (+h) in L2

    const __half* wptr[6];
#pragma unroll
    for (int j = 0; j < 6; j++) {
        int lr = ldrow + j * 16;
        long wr = (long)(lr >> 5) * NHH + n0 + (lr & 31);
        wptr[j] = gWhh + wr * (long)NHH + ldseg * 8;
    }
    long aoffg[2];
#pragma unroll
    for (int j = 0; j < 2; j++) aoffg[j] = (long)(ldrow + j * 16) * NHH + ldseg * 8;

    uint32_t aoff = (wm * 16 + (lane & 15)) * LD + (lane >> 4) * 8;
    uint32_t woff4 = (wn * 24 + ((lane >> 4) & 1) * 8 + (lane & 7)) * LD
                     + ((lane >> 3) & 1) * 8;
    uint32_t woff2 = (wn * 24 + 16 + (lane & 7)) * LD + ((lane >> 3) & 1) * 8;

    uint32_t As_base = smem_u32(As);
    uint32_t Ws_base = smem_u32(Ws);

    int pb[4], pn[4];
    float hreg[4], bhr[4], bhz[4], bhn[4];
#pragma unroll
    for (int i = 0; i < 4; i++) {
        int idx = tid + i * 256;
        pb[i] = idx >> 5;
        pn[i] = n0 + (idx & 31);
        hreg[i] = h0[pn[i]];
        bhr[i] = b_hh[pn[i]];
        bhz[i] = b_hh[NHH + pn[i]];
        bhn[i] = b_hh[2 * NHH + pn[i]];
    }

    unsigned barBase = *(volatile unsigned*)&gBarPhase;

    // prologue: ST-1 W groups, ST-1 A groups
#pragma unroll
    for (int s = 0; s < ST - 1; s++) {
        int k0 = s * BK;
#pragma unroll
        for (int j = 0; j < 6; j++) {
            int lr = ldrow + j * 16;
            cp_async16_el(Ws + (s * WR + lr) * LD + ldseg * 8, wptr[j] + k0, pol);
        }
        cp_commit();
    }
    {
        const __half* A0 = gHh[0];
#pragma unroll
        for (int s = 0; s < ST - 1; s++) {
#pragma unroll
            for (int j = 0; j < 2; j++)
                cp_async16_el(As + (s * AR + ldrow + j * 16) * LD + ldseg * 8,
                              A0 + aoffg[j] + s * BK, pol);
            cp_commit();
        }
    }

    const int KT = NHH / BK;  // 32
    for (int t = 0; t < NTT; t++) {
        const __half* Ain = gHh[t & 1];
        __half* Aout = gHh[(t + 1) & 1];

        // gx prefetch with streaming hint (evict_first; read once)
        float pxr[4], pxz[4], pxn[4];
#pragma unroll
        for (int i = 0; i < 4; i++) {
            long gxr = ((long)(t * NB + pb[i])) * NH3 + pn[i];
            pxr[i] = __ldcs(&gGx[gxr]);
            pxz[i] = __ldcs(&gGx[gxr + NHH]);
            pxn[i] = __ldcs(&gGx[gxr + 2 * NHH]);
        }

        float acc[3][4];
#pragma unroll
        for (int nt = 0; nt < 3; nt++)
#pragma unroll
            for (int q = 0; q < 4; q++) acc[nt][q] = 0.f;

        for (int kt = 0; kt < KT; kt++) {
            cp_wait<ST - 2>();
            __syncthreads();
            if (kt + ST - 1 < KT) {
                int s = (kt + ST - 1) & (ST - 1);
                int k0 = (kt + ST - 1) * BK;
#pragma unroll
                for (int j = 0; j < 2; j++)
                    cp_async16_el(As + (s * AR + ldrow + j * 16) * LD + ldseg * 8,
                                  Ain + aoffg[j] + k0, pol);
#pragma unroll
                for (int j = 0; j < 6; j++) {
                    int lr = ldrow + j * 16;
                    cp_async16_el(Ws + (s * WR + lr) * LD + ldseg * 8, wptr[j] + k0, pol);
                }
            }
            cp_commit();  // every iteration (tail alignment)

            uint32_t Ab = As_base + (uint32_t)((kt & (ST - 1)) * AR * LD) * 2;
            uint32_t Wb = Ws_base + (uint32_t)((kt & (ST - 1)) * WR * LD) * 2;

#pragma unroll
            for (int kk = 0; kk < BK; kk += 16) {
                uint32_t af[4];
                ldsm_x4(af[0], af[1], af[2], af[3], Ab + (aoff + kk) * 2);
                uint32_t b00, b01, b10, b11, b20, b21;
                ldsm_x4(b00, b01, b10, b11, Wb + (woff4 + kk) * 2);
                ldsm_x2(b20, b21, Wb + (woff2 + kk) * 2);
                mma_m16n8k16(acc[0], af, b00, b01);
                mma_m16n8k16(acc[1], af, b10, b11);
                mma_m16n8k16(acc[2], af, b20, b21);
            }
        }

        // gh -> smem
#pragma unroll
        for (int nt = 0; nt < 3; nt++) {
            int c = (wn * 3 + nt) * 8 + 2 * ti;
            int m = wm * 16 + g;
            gh_s[m * 100 + c]           = acc[nt][0];
            gh_s[m * 100 + c + 1]       = acc[nt][1];
            gh_s[(m + 8) * 100 + c]     = acc[nt][2];
            gh_s[(m + 8) * 100 + c + 1] = acc[nt][3];
        }
        __syncthreads();

#pragma unroll
        for (int i = 0; i < 4; i++) {
            int b = pb[i], nl = pn[i] - n0, n = pn[i];

            float hr = gh_s[b * 100 + nl]      + bhr[i];
            float hz = gh_s[b * 100 + 32 + nl] + bhz[i];
            float hn = gh_s[b * 100 + 64 + nl] + bhn[i];

            float r = 1.f / (1.f + expf(-(pxr[i] + hr)));
            float z = 1.f / (1.f + expf(-(pxz[i] + hz)));
            float nn = tanhf(pxn[i] + r * hn);
            float hnew = (1.f - z) * nn + z * hreg[i];
            hreg[i] = hnew;

            Aout[b * NHH + n] = __float2half(hnew);
            // states: streamed out, never read again by this kernel
            __stcs(&d_out[OUT_STATES + (long)b * (NHH * NTT) + (long)n * NTT + t], hnew);
            if (t == NTT - 1) d_out[OUT_HENC + b * NHH + n] = hnew;
        }

        if (t < NTT - 1) {
            // next-step W stages before barrier (barrier-independent)
#pragma unroll
            for (int s = 0; s < ST - 1; s++) {
                int k0 = s * BK;
#pragma unroll
                for (int j = 0; j < 6; j++) {
                    int lr = ldrow + j * 16;
                    cp_async16_el(Ws + (s * WR + lr) * LD + ldseg * 8, wptr[j] + k0, pol);
                }
                cp_commit();
            }

            // grid barrier (hidden behind W loads)
            __syncthreads();
            if (tid == 0) {
                __threadfence();
                unsigned arrived = atomicAdd(&gBarCnt, 1u);
                unsigned target = barBase + (unsigned)(t + 1);
                if (arrived == NBLK - 1) {
                    gBarCnt = 0;
                    __threadfence();
                    atomicExch(&gBarPhase, target);
                } else {
                    while ((int)(atomicAdd(&gBarPhase, 0u) - target) < 0) {
                        __nanosleep(32);
                    }
                }
            }
            __syncthreads();

            // next-step A stages (h for t+1 globally ready)
            const __half* A2 = gHh[(t + 1) & 1];
#pragma unroll
            for (int s = 0; s < ST - 1; s++) {
#pragma unroll
                for (int j = 0; j < 2; j++)
                    cp_async16_el(As + (s * AR + ldrow + j * 16) * LD + ldseg * 8,
                                  A2 + aoffg[j] + s * BK, pol);
                cp_commit();
            }
        }
    }
    cp_wait<0>();
}

// ------------------------- classifier ---------------------------------------
__global__ void classifier_kernel(const float* __restrict__ w1, const float* __restrict__ b1,
                                  const float* __restrict__ w2, const float* __restrict__ b2,
                                  float* __restrict__ d_out) {
    __shared__ float hid[300];
    int b = blockIdx.x;
    int tid = threadIdx.x, warp = tid >> 5, lane = tid & 31;
    const float* hb = d_out + OUT_HENC + (long)b * NHH;

    for (int j = warp; j < 300; j += 8) {
        float s = 0.f;
        for (int k = lane; k < NHH; k += 32) s += hb[k] * w1[(long)j * NHH + k];
#pragma unroll
        for (int off = 16; off; off >>= 1) s += __shfl_xor_sync(0xffffffffu, s, off);
        if (lane == 0) hid[j] = fmaxf(s + b1[j], 0.f);
    }
    __syncthreads();
    if (warp < 2) {
        float s = 0.f;
        for (int j = lane; j < 300; j += 32) s += hid[j] * w2[warp * 300 + j];
#pragma unroll
        for (int off = 16; off; off >>= 1) s += __shfl_xor_sync(0xffffffffu, s, off);
        if (lane == 0) d_out[OUT_CLS + b * 2 + warp] = s + b2[warp];
    }
}

// ------------------------- launch --------------------------------------------
extern "C" void kernel_launch(void* const* d_in, const int* in_sizes, int n_in,
                              void* d_out, int out_size) {
    const float* x      = (const float*)d_in[0];
    const float* adj    = (const float*)d_in[1];
    const float* h0     = (const float*)d_in[3];
    const float* conv_w = (const float*)d_in[4];
    const float* conv_b = (const float*)d_in[5];
    const float* w_ih   = (const float*)d_in[6];
    const float* w_hh   = (const float*)d_in[7];
    const float* b_ih   = (const float*)d_in[8];
    const float* b_hh   = (const float*)d_in[9];
    const float* cls_w1 = (const float*)d_in[10];
    const float* cls_b1 = (const float*)d_in[11];
    const float* cls_w2 = (const float*)d_in[12];
    const float* cls_b2 = (const float*)d_in[13];
    float* out = (float*)d_out;

    const int REPR_SMEM = (128 * 129 + 32 * 132 + 32 * 132 + 12 * 128) * 4;  // 105984
    const int GX_SMEM   = 3 * (128 + 128) * 72 * 2;                          // 110592
    const int PS_SMEM   = 4 * (32 + 96) * 136 * 2 + 32 * 100 * 4;            // 152064
    cudaFuncSetAttribute(repr_kernel, cudaFuncAttributeMaxDynamicSharedMemorySize, REPR_SMEM);
    cudaFuncSetAttribute(gemm_gx_kernel, cudaFuncAttributeMaxDynamicSharedMemorySize, GX_SMEM);
    cudaFuncSetAttribute(gru_persistent_kernel, cudaFuncAttributeMaxDynamicSharedMemorySize, PS_SMEM);

    // Launch order: gru_persistent at index 3 (the ncu capture slot).
    init_kernel<<<2048, 256>>>((const float4*)w_ih, (const float4*)w_hh, adj, h0);
    repr_kernel<<<NR, 256, REPR_SMEM>>>(x, conv_w, conv_b, out);
    gemm_gx_kernel<<<dim3(25, 96), 256, GX_SMEM>>>(b_ih);
    gru_persistent_kernel<<<NBLK, 256, PS_SMEM>>>(h0, b_hh, out);
    classifier_kernel<<<NB, 256>>>(cls_w1, cls_b1, cls_w2, cls_b2, out);
}

// round 11
// speedup vs baseline: 1.3602x; 1.1403x over previous
#include <cuda_runtime.h>
#include <cuda_fp16.h>
#include <cstdint>
#include <math.h>

// Problem dims
#define NB   32
#define NI   12
#define NVV  128
#define NHD  32
#define NTT  100
#define NHH  4096
#define NH3  12288
#define NR   3200
#define NBLK 128

// d_out region offsets (floats)
static const long OUT_STATES = 13107200L;
static const long OUT_HENC   = 26214400L;
static const long OUT_CLS    = 26345472L;

// ------------------------- scratch -----------------------------------------
__device__ float    gSupport[NVV * NVV];
__device__ __align__(256) __half gReprH[(long)NR * NHH];
__device__ __align__(256) __half gWih[(long)NH3 * NHH];
// W_hh in block-tiled, pre-swizzled layout:
// [block j][kt 0..31][chunk 0..5][2048 halves], chunk = gate*2 + khalf,
// physical byte q within 4KB chunk holds logical l = q ^ ((q>>3)&0x70),
// logical l -> row r = l>>7 (0..31), col c = (l&127)/2 (0..63):
//   W[gate*4096 + j*32 + r][kt*128 + khalf*64 + c]
__device__ __align__(256) __half gWhh[(long)NH3 * NHH];
__device__ __align__(256) float  gGx[(long)NR * NH3];
__device__ __align__(256) __half gHh[2][NB * NHH];
__device__ unsigned gBarCnt;
__device__ unsigned gBarPhase;

// ------------------------- asm helpers -------------------------------------
__device__ __forceinline__ uint64_t mk_evict_last_policy() {
    uint64_t pol;
    asm("createpolicy.fractional.L2::evict_last.b64 %0, 1.0;" : "=l"(pol));
    return pol;
}
__device__ __forceinline__ void cp_async16(void* smem, const void* gmem) {
    uint32_t s = (uint32_t)__cvta_generic_to_shared(smem);
    asm volatile("cp.async.cg.shared.global [%0], [%1], 16;\n" :: "r"(s), "l"(gmem));
}
__device__ __forceinline__ void cp_async16_el(void* smem, const void* gmem, uint64_t pol) {
    uint32_t s = (uint32_t)__cvta_generic_to_shared(smem);
    asm volatile("cp.async.cg.shared.global.L2::cache_hint [%0], [%1], 16, %2;\n"
                 :: "r"(s), "l"(gmem), "l"(pol));
}
__device__ __forceinline__ void cp_commit() {
    asm volatile("cp.async.commit_group;\n");
}
template <int N>
__device__ __forceinline__ void cp_wait() {
    asm volatile("cp.async.wait_group %0;\n" :: "n"(N));
}
__device__ __forceinline__ uint32_t smem_u32(const void* p) {
    return (uint32_t)__cvta_generic_to_shared(p);
}
__device__ __forceinline__ void ldsm_x4(uint32_t& r0, uint32_t& r1, uint32_t& r2,
                                        uint32_t& r3, uint32_t addr) {
    asm volatile("ldmatrix.sync.aligned.m8n8.x4.shared.b16 {%0,%1,%2,%3}, [%4];\n"
                 : "=r"(r0), "=r"(r1), "=r"(r2), "=r"(r3) : "r"(addr));
}
__device__ __forceinline__ void ldsm_x2(uint32_t& r0, uint32_t& r1, uint32_t addr) {
    asm volatile("ldmatrix.sync.aligned.m8n8.x2.shared.b16 {%0,%1}, [%2];\n"
                 : "=r"(r0), "=r"(r1) : "r"(addr));
}
__device__ __forceinline__ void mma_m16n8k16(float* d, const uint32_t* a,
                                             uint32_t b0, uint32_t b1) {
    asm volatile(
        "mma.sync.aligned.m16n8k16.row.col.f32.f16.f16.f32 "
        "{%0,%1,%2,%3}, {%4,%5,%6,%7}, {%8,%9}, {%0,%1,%2,%3};\n"
        : "+f"(d[0]), "+f"(d[1]), "+f"(d[2]), "+f"(d[3])
        : "r"(a[0]), "r"(a[1]), "r"(a[2]), "r"(a[3]), "r"(b0), "r"(b1));
}
__device__ __forceinline__ void mbar_init(uint32_t addr, uint32_t cnt) {
    asm volatile("mbarrier.init.shared.b64 [%0], %1;" :: "r"(addr), "r"(cnt) : "memory");
}
__device__ __forceinline__ void mbar_expect_tx(uint32_t addr, uint32_t bytes) {
    asm volatile("mbarrier.arrive.expect_tx.shared.b64 _, [%0], %1;"
                 :: "r"(addr), "r"(bytes) : "memory");
}
__device__ __forceinline__ void mbar_wait_parity(uint32_t addr, uint32_t parity) {
    uint32_t done;
    asm volatile(
        "{\n\t.reg .pred p;\n\t"
        "mbarrier.try_wait.parity.acquire.cta.shared::cta.b64 p, [%1], %2;\n\t"
        "selp.b32 %0, 1, 0, p;\n\t}"
        : "=r"(done) : "r"(addr), "r"(parity) : "memory");
    if (!done) {
        asm volatile(
            "{\n\t.reg .pred P1;\n\t"
            "WAIT_LOOP_%=:\n\t"
            "mbarrier.try_wait.parity.acquire.cta.shared::cta.b64 P1, [%0], %1, 0x989680;\n\t"
            "@P1 bra.uni WAIT_DONE_%=;\n\t"
            "bra.uni WAIT_LOOP_%=;\n\t"
            "WAIT_DONE_%=:\n\t}"
            :: "r"(addr), "r"(parity) : "memory");
    }
}
__device__ __forceinline__ void tma_bulk_1d(uint32_t smem_dst, const void* gsrc,
                                            uint32_t bytes, uint32_t mbar) {
    asm volatile(
        "cp.async.bulk.shared::cluster.global.mbarrier::complete_tx::bytes "
        "[%0], [%1], %2, [%3];"
        :: "r"(smem_dst), "l"(gsrc), "r"(bytes), "r"(mbar) : "memory");
}

// ------------------------- init: weights + support + h0 ---------------------
__global__ void init_kernel(const float4* __restrict__ wih4,
                            const float* __restrict__ whh,
                            const float* __restrict__ adj,
                            const float* __restrict__ h0) {
    long gid = (long)blockIdx.x * blockDim.x + threadIdx.x;
    long stride = (long)gridDim.x * blockDim.x;

    if (blockIdx.x == 0 && threadIdx.x < NVV) {
        int w = threadIdx.x;
        float s = 0.f;
        for (int v = 0; v < NVV; v++) s += adj[w * NVV + v];
        float inv = 1.f / (s + 1e-6f);
        for (int v = 0; v < NVV; v++) gSupport[w * NVV + v] = adj[w * NVV + v] * inv;
    }

    if (gid < (long)NB * NHH) {
        gHh[0][gid] = __float2half(h0[gid & (NHH - 1)]);
    }

    // W_ih: plain fp16 convert
    long n4 = (long)NH3 * NHH / 4;
    __half2* wih_o = (__half2*)gWih;
    for (long i = gid; i < n4; i += stride) {
        float4 a = wih4[i];
        wih_o[2 * i]     = __floats2half2_rn(a.x, a.y);
        wih_o[2 * i + 1] = __floats2half2_rn(a.z, a.w);
    }

    // W_hh: block-tiled + SW128-swizzled fp16
    long ntot = (long)NH3 * NHH;   // halves
    for (long idx = gid; idx < ntot; idx += stride) {
        int  p       = (int)(idx & 2047);
        long chunkid = idx >> 11;
        int  ch      = (int)(chunkid % 6);
        long jk      = chunkid / 6;
        int  kt      = (int)(jk & 31);
        int  j       = (int)(jk >> 5);
        int  gate    = ch >> 1, khalf = ch & 1;
        int  q = p * 2;
        int  l = q ^ ((q >> 3) & 0x70);
        int  r = l >> 7;
        int  c = (l & 127) >> 1;
        long wrow = (long)gate * NHH + j * 32 + r;
        long wcol = (long)kt * 128 + khalf * 64 + c;
        gWhh[idx] = __float2half(whh[wrow * NHH + wcol]);
    }
}

// ------------------------- repr --------------------------------------------
__global__ void repr_kernel(const float* __restrict__ x,
                            const float* __restrict__ conv_w,
                            const float* __restrict__ conv_b,
                            float* __restrict__ d_out) {
    extern __shared__ float sm[];
    float* supT = sm;
    float* bufA = supT + 128 * 129;
    float* bufB = bufA + 32 * 132;
    float* xs   = bufB + 32 * 132;

    int r = blockIdx.x;
    int t = r >> 5;
    int b = r & 31;
    int tid = threadIdx.x;

    for (int idx = tid; idx < NI * NVV; idx += 256) {
        int i = idx >> 7, v = idx & 127;
        xs[idx] = x[(((long)b * NI + i) * NVV + v) * NTT + t];
    }
    for (int idx = tid; idx < NVV * NVV; idx += 256) {
        int w = idx >> 7, v = idx & 127;
        supT[v * 129 + w] = gSupport[idx];
    }
    __syncthreads();

    for (int idx = tid; idx < NHD * NVV; idx += 256) {
        int h = idx >> 7, v = idx & 127;
        float a = conv_b[h];
#pragma unroll
        for (int i = 0; i < NI; i++) a += conv_w[h * NI + i] * xs[i * NVV + v];
        bufA[h * 132 + v] = a;
    }
    __syncthreads();

    int w0 = tid & 31;
    int h0 = tid >> 5;

    float acc1[4][4];
#pragma unroll
    for (int i = 0; i < 4; i++)
#pragma unroll
        for (int j = 0; j < 4; j++) acc1[i][j] = 0.f;
    for (int v = 0; v < NVV; v++) {
        float a[4], s[4];
#pragma unroll
        for (int i = 0; i < 4; i++) a[i] = bufA[(h0 + 8 * i) * 132 + v];
#pragma unroll
        for (int j = 0; j < 4; j++) s[j] = supT[v * 129 + w0 + 32 * j];
#pragma unroll
        for (int i = 0; i < 4; i++)
#pragma unroll
            for (int j = 0; j < 4; j++) acc1[i][j] += a[i] * s[j];
    }
    __syncthreads();
#pragma unroll
    for (int i = 0; i < 4; i++)
#pragma unroll
        for (int j = 0; j < 4; j++) bufB[(h0 + 8 * i) * 132 + w0 + 32 * j] = acc1[i][j];
    __syncthreads();

    float acc2[4][4];
#pragma unroll
    for (int i = 0; i < 4; i++)
#pragma unroll
        for (int j = 0; j < 4; j++) acc2[i][j] = 0.f;
    for (int v = 0; v < NVV; v++) {
        float a[4], s[4];
#pragma unroll
        for (int i = 0; i < 4; i++) a[i] = bufB[(h0 + 8 * i) * 132 + v];
#pragma unroll
        for (int j = 0; j < 4; j++) s[j] = supT[v * 129 + w0 + 32 * j];
#pragma unroll
        for (int i = 0; i < 4; i++)
#pragma unroll
            for (int j = 0; j < 4; j++) acc2[i][j] += a[i] * s[j];
    }

#pragma unroll
    for (int i = 0; i < 4; i++) {
#pragma unroll
        for (int j = 0; j < 4; j++) {
            int h = h0 + 8 * i, w = w0 + 32 * j;
            int n = h * NVV + w;
            float val = acc2[i][j];
            d_out[(long)b * (NHH * NTT) + (long)n * NTT + t] = val;
            gReprH[(long)r * NHH + n] = __float2half(val);
        }
    }
}

// ------------------------- pipelined gx GEMM (ST=3, 2 CTA/SM) --------------
__global__ void __launch_bounds__(256, 2) gemm_gx_kernel(const float* __restrict__ bias) {
    constexpr int BM = 128, BN = 128, BK = 64, ST = 3, LD = 72;
    extern __shared__ __half smh[];
    __half* As = smh;
    __half* Ws = smh + ST * BM * LD;

    int tid = threadIdx.x;
    int warp = tid >> 5, lane = tid & 31;
    int g = lane >> 2, ti = lane & 3;
    int wm = warp & 1, wn = warp >> 1;

    long rowA0 = (long)blockIdx.x * BM;   // M-tile (25)
    long rowW0 = (long)blockIdx.y * BN;   // N-tile (96)

    const __half* A = gReprH;
    const __half* W = gWih;

    int ldrow = tid >> 3, ldseg = tid & 7;
    uint64_t pol = mk_evict_last_policy();

    uint32_t aoff[4];
#pragma unroll
    for (int mt = 0; mt < 4; mt++)
        aoff[mt] = (wm * 64 + mt * 16 + (lane & 15)) * LD + (lane >> 4) * 8;
    uint32_t woff[2];
#pragma unroll
    for (int pr = 0; pr < 2; pr++)
        woff[pr] = (wn * 32 + pr * 16 + ((lane >> 4) & 1) * 8 + (lane & 7)) * LD
                   + ((lane >> 3) & 1) * 8;

    uint32_t As_base = smem_u32(As);
    uint32_t Ws_base = smem_u32(Ws);

#pragma unroll
    for (int s = 0; s < ST - 1; s++) {
        int k0 = s * BK;
#pragma unroll
        for (int i = 0; i < 4; i++) {
            int row = ldrow + i * 32;
            cp_async16_el(As + (s * BM + row) * LD + ldseg * 8,
                          A + (rowA0 + row) * (long)NHH + k0 + ldseg * 8, pol);
        }
#pragma unroll
        for (int i = 0; i < 4; i++) {
            int row = ldrow + i * 32;
            cp_async16(Ws + (s * BN + row) * LD + ldseg * 8,
                       W + (rowW0 + row) * (long)NHH + k0 + ldseg * 8);
        }
        cp_commit();
    }

    float acc[4][4][4];
#pragma unroll
    for (int mt = 0; mt < 4; mt++)
#pragma unroll
        for (int nt = 0; nt < 4; nt++)
#pragma unroll
            for (int q = 0; q < 4; q++) acc[mt][nt][q] = 0.f;

    const int KT = NHH / BK;
    for (int kt = 0; kt < KT; kt++) {
        cp_wait<ST - 2>();
        __syncthreads();
        if (kt + ST - 1 < KT) {
            int s = (kt + ST - 1) % ST;
            int k0 = (kt + ST - 1) * BK;
#pragma unroll
            for (int i = 0; i < 4; i++) {
                int row = ldrow + i * 32;
                cp_async16_el(As + (s * BM + row) * LD + ldseg * 8,
                              A + (rowA0 + row) * (long)NHH + k0 + ldseg * 8, pol);
            }
#pragma unroll
            for (int i = 0; i < 4; i++) {
                int row = ldrow + i * 32;
                cp_async16(Ws + (s * BN + row) * LD + ldseg * 8,
                           W + (rowW0 + row) * (long)NHH + k0 + ldseg * 8);
            }
        }
        cp_commit();  // every iter (tail alignment)

        uint32_t Ab = As_base + (uint32_t)((kt % ST) * BM * LD) * 2;
        uint32_t Wb = Ws_base + (uint32_t)((kt % ST) * BN * LD) * 2;

#pragma unroll
        for (int kk = 0; kk < BK; kk += 16) {
            uint32_t af[4][4];
#pragma unroll
            for (int mt = 0; mt < 4; mt++)
                ldsm_x4(af[mt][0], af[mt][1], af[mt][2], af[mt][3],
                        Ab + (aoff[mt] + kk) * 2);
            uint32_t bf[4][2];
#pragma unroll
            for (int pr = 0; pr < 2; pr++)
                ldsm_x4(bf[2 * pr][0], bf[2 * pr][1], bf[2 * pr + 1][0], bf[2 * pr + 1][1],
                        Wb + (woff[pr] + kk) * 2);
#pragma unroll
            for (int nt = 0; nt < 4; nt++)
#pragma unroll
                for (int mt = 0; mt < 4; mt++)
                    mma_m16n8k16(acc[mt][nt], af[mt], bf[nt][0], bf[nt][1]);
        }
    }

    float* C = gGx;
#pragma unroll
    for (int mt = 0; mt < 4; mt++) {
        long row = rowA0 + wm * 64 + mt * 16 + g;
#pragma unroll
        for (int nt = 0; nt < 4; nt++) {
            long col = rowW0 + wn * 32 + nt * 8 + 2 * ti;
            float bv0 = bias[col], bv1 = bias[col + 1];
            __stcs(&C[row * NH3 + col],           acc[mt][nt][0] + bv0);
            __stcs(&C[row * NH3 + col + 1],       acc[mt][nt][1] + bv1);
            __stcs(&C[(row + 8) * NH3 + col],     acc[mt][nt][2] + bv0);
            __stcs(&C[(row + 8) * NH3 + col + 1], acc[mt][nt][3] + bv1);
        }
    }
}

// ------------------------- persistent GRU: TMA-bulk W + cp.async A ----------
// W pipeline: 6-stage mbarrier ring, one 24KB cp.async.bulk per kt (continuous
// tile stream across steps -> bypasses per-SM L1tex wavefront queue).
// A pipeline: 4-stage cp.async groups (small; 8KB/kt).
// smem: W 6*24576 | A 4*32*136*2 | gh_s 32*100*4 | 6 mbarriers
__global__ void __launch_bounds__(256) gru_persistent_kernel(
    const float* __restrict__ h0,
    const float* __restrict__ b_hh,
    float* __restrict__ d_out) {
    constexpr int BK = 128, STA = 4, STW = 6, LDA = 136, AR = 32, KT = 32;
    constexpr int WTILE = 24576;  // bytes per W kt-tile
    extern __shared__ __align__(1024) char smraw[];
    __half* Ws   = (__half*)smraw;                       // 147456 B
    __half* As   = (__half*)(smraw + 147456);            // 34816 B
    float*  gh_s = (float*)(smraw + 182272);             // 12800 B
    uint32_t wbar0 = smem_u32(smraw + 195072);           // 6 x 8B

    int tid = threadIdx.x;
    int warp = tid >> 5, lane = tid & 31;
    int g = lane >> 2, ti = lane & 3;
    int wm = warp & 1, wn = warp >> 1;
    int n0 = blockIdx.x * 32;
    int ldrow = tid >> 4, ldseg = tid & 15;

    // A ldmatrix offset (halves within an A stage)
    uint32_t aoff = (wm * 16 + (lane & 15)) * LDA + (lane >> 4) * 8;
    // W ldmatrix per-lane (swizzled chunk addressing, bytes within W stage)
    int row4 = wn * 24 + ((lane >> 4) & 1) * 8 + (lane & 7);
    uint32_t wbase4 = (uint32_t)((row4 >> 5) * 8192 + (row4 & 31) * 128);
    uint32_t swz4   = (uint32_t)(((row4 & 31) & 7) << 4);
    uint32_t cb4    = ((lane >> 3) & 1) * 16;
    int row2 = wn * 24 + 16 + (lane & 7);
    uint32_t wbase2 = (uint32_t)((row2 >> 5) * 8192 + (row2 & 31) * 128);
    uint32_t swz2   = (uint32_t)(((row2 & 31) & 7) << 4);
    uint32_t cb2    = ((lane >> 3) & 1) * 16;

    uint32_t As_base = smem_u32(As);
    uint32_t Ws_base = smem_u32(Ws);

    long aoffg[2];
#pragma unroll
    for (int j = 0; j < 2; j++) aoffg[j] = (long)(ldrow + j * 16) * NHH + ldseg * 8;

    int pb[4], pn[4];
    float hreg[4], bhr[4], bhz[4], bhn[4];
#pragma unroll
    for (int i = 0; i < 4; i++) {
        int idx = tid + i * 256;
        pb[i] = idx >> 5;
        pn[i] = n0 + (idx & 31);
        hreg[i] = h0[pn[i]];
        bhr[i] = b_hh[pn[i]];
        bhz[i] = b_hh[NHH + pn[i]];
        bhn[i] = b_hh[2 * NHH + pn[i]];
    }

    unsigned barBase = *(volatile unsigned*)&gBarPhase;
    const __half* wsrc = gWhh + (long)blockIdx.x * KT * 12288;  // 12288 halves/tile

    // mbarrier init (count=1; expect_tx supplies the arrive)
    if (tid == 0) {
        for (int s = 0; s < STW; s++) mbar_init(wbar0 + 8 * s, 1);
    }
    __syncthreads();
    asm volatile("fence.proxy.async.shared::cta;" ::: "memory");

    // W prologue: tiles 0..4 -> stages 0..4
    if (tid == 0) {
#pragma unroll
        for (int s = 0; s < STW - 1; s++) {
            mbar_expect_tx(wbar0 + 8 * s, WTILE);
            tma_bulk_1d(Ws_base + s * WTILE, wsrc + (long)s * 12288, WTILE,
                        wbar0 + 8 * s);
        }
    }
    // A prologue for t=0
    {
        const __half* A0 = gHh[0];
#pragma unroll
        for (int s = 0; s < STA - 1; s++) {
#pragma unroll
            for (int j = 0; j < 2; j++)
                cp_async16(As + (s * AR + ldrow + j * 16) * LDA + ldseg * 8,
                           A0 + aoffg[j] + s * BK);
            cp_commit();
        }
    }

    int cs = 0, cph = 0;     // consumer W cursor
    int si = STW - 1;        // issue W stage cursor

    for (int t = 0; t < NTT; t++) {
        const __half* Ain = gHh[t & 1];
        __half* Aout = gHh[(t + 1) & 1];

        float pxr[4], pxz[4], pxn[4];
#pragma unroll
        for (int i = 0; i < 4; i++) {
            long gxr = ((long)(t * NB + pb[i])) * NH3 + pn[i];
            pxr[i] = __ldcs(&gGx[gxr]);
            pxz[i] = __ldcs(&gGx[gxr + NHH]);
            pxn[i] = __ldcs(&gGx[gxr + 2 * NHH]);
        }

        float acc[3][4];
#pragma unroll
        for (int nt = 0; nt < 3; nt++)
#pragma unroll
            for (int q = 0; q < 4; q++) acc[nt][q] = 0.f;

        for (int kt = 0; kt < KT; kt++) {
            mbar_wait_parity(wbar0 + 8 * cs, (uint32_t)cph);  // W ready (acquire)
            cp_wait<STA - 2>();                                // A ready
            __syncthreads();                                   // all warps past kt-1

            // W issue: tile gkt+5 into stage si == (cs+5)%6 (consumed at kt-1)
            if (t < NTT - 1 || kt < KT - (STW - 1)) {
                if (tid == 0) {
                    int ktn = kt + (STW - 1);
                    if (ktn >= KT) ktn -= KT;
                    mbar_expect_tx(wbar0 + 8 * si, WTILE);
                    tma_bulk_1d(Ws_base + si * WTILE, wsrc + (long)ktn * 12288,
                                WTILE, wbar0 + 8 * si);
                }
                si++; if (si == STW) si = 0;
            }
            // A issue (in-step)
            if (kt + STA - 1 < KT) {
                int s = (kt + STA - 1) & 3;
                int k0 = (kt + STA - 1) * BK;
#pragma unroll
                for (int j = 0; j < 2; j++)
                    cp_async16(As + (s * AR + ldrow + j * 16) * LDA + ldseg * 8,
                               Ain + aoffg[j] + k0);
            }
            cp_commit();  // every iteration (tail alignment)

            uint32_t Ab = As_base + (uint32_t)((kt & 3) * AR * LDA) * 2;
            uint32_t Wb = Ws_base + (uint32_t)(cs * WTILE);

#pragma unroll
            for (int kk = 0; kk < BK; kk += 16) {
                uint32_t af[4];
                ldsm_x4(af[0], af[1], af[2], af[3], Ab + (aoff + kk) * 2);
                uint32_t khb = (uint32_t)((kk >> 6) * 4096);
                uint32_t klb = (uint32_t)((kk & 63) * 2);
                uint32_t b00, b01, b10, b11, b20, b21;
                ldsm_x4(b00, b01, b10, b11,
                        Wb + wbase4 + khb + ((cb4 + klb) ^ swz4));
                ldsm_x2(b20, b21,
                        Wb + wbase2 + khb + ((cb2 + klb) ^ swz2));
                mma_m16n8k16(acc[0], af, b00, b01);
                mma_m16n8k16(acc[1], af, b10, b11);
                mma_m16n8k16(acc[2], af, b20, b21);
            }
            cs++; if (cs == STW) { cs = 0; cph ^= 1; }
        }

        // gh -> smem
#pragma unroll
        for (int nt = 0; nt < 3; nt++) {
            int c = (wn * 3 + nt) * 8 + 2 * ti;
            int m = wm * 16 + g;
            gh_s[m * 100 + c]           = acc[nt][0];
            gh_s[m * 100 + c + 1]       = acc[nt][1];
            gh_s[(m + 8) * 100 + c]     = acc[nt][2];
            gh_s[(m + 8) * 100 + c + 1] = acc[nt][3];
        }
        __syncthreads();

#pragma unroll
        for (int i = 0; i < 4; i++) {
            int b = pb[i], nl = pn[i] - n0, n = pn[i];

            float hr = gh_s[b * 100 + nl]      + bhr[i];
            float hz = gh_s[b * 100 + 32 + nl] + bhz[i];
            float hn = gh_s[b * 100 + 64 + nl] + bhn[i];

            float r = 1.f / (1.f + expf(-(pxr[i] + hr)));
            float z = 1.f / (1.f + expf(-(pxz[i] + hz)));
            float nn = tanhf(pxn[i] + r * hn);
            float hnew = (1.f - z) * nn + z * hreg[i];
            hreg[i] = hnew;

            Aout[b * NHH + n] = __float2half(hnew);
            __stcs(&d_out[OUT_STATES + (long)b * (NHH * NTT) + (long)n * NTT + t], hnew);
            if (t == NTT - 1) d_out[OUT_HENC + b * NHH + n] = hnew;
        }

        if (t < NTT - 1) {
            // grid barrier (W tiles for next step already streaming)
            __syncthreads();
            if (tid == 0) {
                __threadfence();
                unsigned arrived = atomicAdd(&gBarCnt, 1u);
                unsigned target = barBase + (unsigned)(t + 1);
                if (arrived == NBLK - 1) {
                    gBarCnt = 0;
                    __threadfence();
                    atomicExch(&gBarPhase, target);
                } else {
                    while ((int)(atomicAdd(&gBarPhase, 0u) - target) < 0) {
                        __nanosleep(32);
                    }
                }
            }
            __syncthreads();

            // A prologue for next step (h now globally ready)
            const __half* A2 = gHh[(t + 1) & 1];
#pragma unroll
            for (int s = 0; s < STA - 1; s++) {
#pragma unroll
                for (int j = 0; j < 2; j++)
                    cp_async16(As + (s * AR + ldrow + j * 16) * LDA + ldseg * 8,
                               A2 + aoffg[j] + s * BK);
                cp_commit();
            }
        }
    }
    cp_wait<0>();
}

// ------------------------- classifier ---------------------------------------
__global__ void classifier_kernel(const float* __restrict__ w1, const float* __restrict__ b1,
                                  const float* __restrict__ w2, const float* __restrict__ b2,
                                  float* __restrict__ d_out) {
    __shared__ float hid[300];
    int b = blockIdx.x;
    int tid = threadIdx.x, warp = tid >> 5, lane = tid & 31;
    const float* hb = d_out + OUT_HENC + (long)b * NHH;

    for (int j = warp; j < 300; j += 8) {
        float s = 0.f;
        for (int k = lane; k < NHH; k += 32) s += hb[k] * w1[(long)j * NHH + k];
#pragma unroll
        for (int off = 16; off; off >>= 1) s += __shfl_xor_sync(0xffffffffu, s, off);
        if (lane == 0) hid[j] = fmaxf(s + b1[j], 0.f);
    }
    __syncthreads();
    if (warp < 2) {
        float s = 0.f;
        for (int j = lane; j < 300; j += 32) s += hid[j] * w2[warp * 300 + j];
#pragma unroll
        for (int off = 16; off; off >>= 1) s += __shfl_xor_sync(0xffffffffu, s, off);
        if (lane == 0) d_out[OUT_CLS + b * 2 + warp] = s + b2[warp];
    }
}

// ------------------------- launch --------------------------------------------
extern "C" void kernel_launch(void* const* d_in, const int* in_sizes, int n_in,
                              void* d_out, int out_size) {
    const float* x      = (const float*)d_in[0];
    const float* adj    = (const float*)d_in[1];
    const float* h0     = (const float*)d_in[3];
    const float* conv_w = (const float*)d_in[4];
    const float* conv_b = (const float*)d_in[5];
    const float* w_ih   = (const float*)d_in[6];
    const float* w_hh   = (const float*)d_in[7];
    const float* b_ih   = (const float*)d_in[8];
    const float* b_hh   = (const float*)d_in[9];
    const float* cls_w1 = (const float*)d_in[10];
    const float* cls_b1 = (const float*)d_in[11];
    const float* cls_w2 = (const float*)d_in[12];
    const float* cls_b2 = (const float*)d_in[13];
    float* out = (float*)d_out;

    const int REPR_SMEM = (128 * 129 + 32 * 132 + 32 * 132 + 12 * 128) * 4;  // 105984
    const int GX_SMEM   = 3 * (128 + 128) * 72 * 2;                          // 110592
    const int PS_SMEM   = 195072 + 64;                                       // 195136
    cudaFuncSetAttribute(repr_kernel, cudaFuncAttributeMaxDynamicSharedMemorySize, REPR_SMEM);
    cudaFuncSetAttribute(gemm_gx_kernel, cudaFuncAttributeMaxDynamicSharedMemorySize, GX_SMEM);
    cudaFuncSetAttribute(gru_persistent_kernel, cudaFuncAttributeMaxDynamicSharedMemorySize, PS_SMEM);

    // Launch order: gru_persistent at index 3 (the ncu capture slot).
    init_kernel<<<2048, 256>>>((const float4*)w_ih, w_hh, adj, h0);
    repr_kernel<<<NR, 256, REPR_SMEM>>>(x, conv_w, conv_b, out);
    gemm_gx_kernel<<<dim3(25, 96), 256, GX_SMEM>>>(b_ih);
    gru_persistent_kernel<<<NBLK, 256, PS_SMEM>>>(h0, b_hh, out);
    classifier_kernel<<<NB, 256>>>(cls_w1, cls_b1, cls_w2, cls_b2, out);
}